// round 11
// baseline (speedup 1.0000x reference)
#include <cuda_runtime.h>
#include <math.h>

#define BATCH 2
#define SEQ   2048
#define EMB   1024
#define NH    16
#define HD    64
#define PHH   8      // pnp heads
#define LM    64     // landmarks
#define NBH   16     // BATCH * PHH
#define QSCALE 0.125f
#define LSTRIDE 32   // SEQ / LM
#define NCHUNK 16    // ecv split-K chunks

// ---------------- scratch (device globals; no runtime allocation) ----------------
__device__ float g_q[BATCH*NH*SEQ*HD];
__device__ float g_k[BATCH*NH*SEQ*HD];
__device__ float g_v[BATCH*NH*SEQ*HD];
__device__ float g_SC[NBH*LM*SEQ];          // q_m @ k^T per pnp head
__device__ float g_scmax[NBH*LM];
__device__ float g_esum[NBH*LM];            // rowsum of eC
__device__ float g_mid0p[NCHUNK*NBH*LM*HD]; // split-K partials of eC @ v_p
__device__ float g_eB[NBH*LM*LM];
__device__ float g_T[NBH*LM*LM];            // pinv temp
__device__ float g_U[NBH*LM*LM];            // pinv temp
__device__ float g_colmax[NBH];
__device__ float g_rowmax[NBH];
__device__ float g_mid[NBH*LM*(HD+1)];      // pi @ (eC @ v_aug), 65 cols
__device__ float g_ctx[BATCH*SEQ*EMB];

// ---------------- tf32 mma helpers ----------------
__device__ __forceinline__ unsigned f2tf32(float x) {
    unsigned r;
    asm("cvt.rna.tf32.f32 %0, %1;" : "=r"(r) : "f"(x));
    return r;
}
__device__ __forceinline__ void mma8(float* c, const unsigned* a, const unsigned* b) {
    asm volatile(
        "mma.sync.aligned.m16n8k8.row.col.f32.tf32.tf32.f32 "
        "{%0,%1,%2,%3},{%4,%5,%6,%7},{%8,%9},{%0,%1,%2,%3};\n"
        : "+f"(c[0]), "+f"(c[1]), "+f"(c[2]), "+f"(c[3])
        : "r"(a[0]), "r"(a[1]), "r"(a[2]), "r"(a[3]), "r"(b[0]), "r"(b[1]));
}
__device__ __forceinline__ uint4 cvt4(float4 v) {
    uint4 u;
    u.x = f2tf32(v.x); u.y = f2tf32(v.y); u.z = f2tf32(v.z); u.w = f2tf32(v.w);
    return u;
}

// ======================= K1: QKV GEMM (tf32, 128x128x32, 2-stage pipeline) =======================
#define ATILE (128*36)
#define GEMM_SMEM (2 * 2 * ATILE * 4)   // 73728 B
__global__ __launch_bounds__(256) void qkv_gemm_tf32(const float* __restrict__ X,
                                                     const float* __restrict__ W,
                                                     const float* __restrict__ bias) {
    extern __shared__ unsigned dsm[];
    unsigned* As = dsm;              // [2][128][36]
    unsigned* Bs = dsm + 2*ATILE;    // [2][128][36]
    const int bi = blockIdx.y * 128;
    const int bj = blockIdx.x * 128;
    const int tid = threadIdx.x, warp = tid >> 5, lane = tid & 31;
    const int g = lane >> 2, tig = lane & 3;
    const int wm = (warp & 1) * 64, wn = (warp >> 1) * 32;
    float c[4][4][4] = {};
    const int lr = tid >> 1, lc = (tid & 1) * 16;
    const float* ax = X + (bi + lr) * EMB + lc;
    const float* bx = W + (bj + lr) * EMB + lc;
    float4 pa[4], pb[4];
    #pragma unroll
    for (int i = 0; i < 4; i++) {
        pa[i] = *(const float4*)(ax + i*4);
        pb[i] = *(const float4*)(bx + i*4);
    }
    // store tile 0 into buffer 0
    #pragma unroll
    for (int i = 0; i < 4; i++) {
        *(uint4*)&As[lr*36 + lc + i*4] = cvt4(pa[i]);
        *(uint4*)&Bs[lr*36 + lc + i*4] = cvt4(pb[i]);
    }
    int buf = 0;
    for (int k0 = 0; k0 < EMB; k0 += 32, buf ^= 1) {
        __syncthreads();
        const bool nxt = (k0 + 32 < EMB);
        if (nxt) {
            #pragma unroll
            for (int i = 0; i < 4; i++) {
                pa[i] = *(const float4*)(ax + k0 + 32 + i*4);
                pb[i] = *(const float4*)(bx + k0 + 32 + i*4);
            }
        }
        const unsigned* Ab = As + buf*ATILE;
        const unsigned* Bb = Bs + buf*ATILE;
        #pragma unroll
        for (int ks = 0; ks < 4; ks++) {
            unsigned a[4][4], bb[4][2];
            #pragma unroll
            for (int mf = 0; mf < 4; mf++) {
                const unsigned* p = &Ab[(wm + mf*16 + g)*36 + ks*8 + tig];
                a[mf][0] = p[0];
                a[mf][1] = p[8*36];
                a[mf][2] = p[4];
                a[mf][3] = p[8*36 + 4];
            }
            #pragma unroll
            for (int nf = 0; nf < 4; nf++) {
                const unsigned* p = &Bb[(wn + nf*8 + g)*36 + ks*8 + tig];
                bb[nf][0] = p[0];
                bb[nf][1] = p[4];
            }
            #pragma unroll
            for (int mf = 0; mf < 4; mf++)
                #pragma unroll
                for (int nf = 0; nf < 4; nf++)
                    mma8(c[mf][nf], a[mf], bb[nf]);
        }
        if (nxt) {
            unsigned* Aw = As + (buf^1)*ATILE;
            unsigned* Bw = Bs + (buf^1)*ATILE;
            #pragma unroll
            for (int i = 0; i < 4; i++) {
                *(uint4*)&Aw[lr*36 + lc + i*4] = cvt4(pa[i]);
                *(uint4*)&Bw[lr*36 + lc + i*4] = cvt4(pb[i]);
            }
        }
    }
    // epilogue: scatter into q/k/v [B][H][N][D], scale q
    #pragma unroll
    for (int mf = 0; mf < 4; mf++) {
        #pragma unroll
        for (int nf = 0; nf < 4; nf++) {
            int gj = bj + wn + nf*8 + tig*2;
            int s  = gj >> 10;
            int hh = (gj >> 6) & 15;
            int dd = gj & 63;
            float b0 = bias[gj], b1 = bias[gj + 1];
            float* dst = (s == 0) ? g_q : (s == 1) ? g_k : g_v;
            float mul = (s == 0) ? QSCALE : 1.0f;
            int gi = bi + wm + mf*16 + g;
            int bb2 = gi >> 11, n = gi & 2047;
            float2 v0 = make_float2((c[mf][nf][0] + b0) * mul, (c[mf][nf][1] + b1) * mul);
            *(float2*)&dst[((bb2*NH + hh)*SEQ + n)*HD + dd] = v0;
            float2 v1 = make_float2((c[mf][nf][2] + b0) * mul, (c[mf][nf][3] + b1) * mul);
            *(float2*)&dst[((bb2*NH + hh)*SEQ + n + 8)*HD + dd] = v1;
        }
    }
}

// ======================= K8: output projection GEMM (tf32, 2-stage pipeline) =======================
__global__ __launch_bounds__(256) void proj_gemm_tf32(const float* __restrict__ W,
                                                      const float* __restrict__ bias,
                                                      float* __restrict__ out) {
    extern __shared__ unsigned dsm[];
    unsigned* As = dsm;
    unsigned* Bs = dsm + 2*ATILE;
    const int bi = blockIdx.y * 128;
    const int bj = blockIdx.x * 128;
    const int tid = threadIdx.x, warp = tid >> 5, lane = tid & 31;
    const int g = lane >> 2, tig = lane & 3;
    const int wm = (warp & 1) * 64, wn = (warp >> 1) * 32;
    float c[4][4][4] = {};
    const int lr = tid >> 1, lc = (tid & 1) * 16;
    const float* ax = g_ctx + (bi + lr) * EMB + lc;
    const float* bx = W + (bj + lr) * EMB + lc;
    float4 pa[4], pb[4];
    #pragma unroll
    for (int i = 0; i < 4; i++) {
        pa[i] = *(const float4*)(ax + i*4);
        pb[i] = *(const float4*)(bx + i*4);
    }
    #pragma unroll
    for (int i = 0; i < 4; i++) {
        *(uint4*)&As[lr*36 + lc + i*4] = cvt4(pa[i]);
        *(uint4*)&Bs[lr*36 + lc + i*4] = cvt4(pb[i]);
    }
    int buf = 0;
    for (int k0 = 0; k0 < EMB; k0 += 32, buf ^= 1) {
        __syncthreads();
        const bool nxt = (k0 + 32 < EMB);
        if (nxt) {
            #pragma unroll
            for (int i = 0; i < 4; i++) {
                pa[i] = *(const float4*)(ax + k0 + 32 + i*4);
                pb[i] = *(const float4*)(bx + k0 + 32 + i*4);
            }
        }
        const unsigned* Ab = As + buf*ATILE;
        const unsigned* Bb = Bs + buf*ATILE;
        #pragma unroll
        for (int ks = 0; ks < 4; ks++) {
            unsigned a[4][4], bb[4][2];
            #pragma unroll
            for (int mf = 0; mf < 4; mf++) {
                const unsigned* p = &Ab[(wm + mf*16 + g)*36 + ks*8 + tig];
                a[mf][0] = p[0];
                a[mf][1] = p[8*36];
                a[mf][2] = p[4];
                a[mf][3] = p[8*36 + 4];
            }
            #pragma unroll
            for (int nf = 0; nf < 4; nf++) {
                const unsigned* p = &Bb[(wn + nf*8 + g)*36 + ks*8 + tig];
                bb[nf][0] = p[0];
                bb[nf][1] = p[4];
            }
            #pragma unroll
            for (int mf = 0; mf < 4; mf++)
                #pragma unroll
                for (int nf = 0; nf < 4; nf++)
                    mma8(c[mf][nf], a[mf], bb[nf]);
        }
        if (nxt) {
            unsigned* Aw = As + (buf^1)*ATILE;
            unsigned* Bw = Bs + (buf^1)*ATILE;
            #pragma unroll
            for (int i = 0; i < 4; i++) {
                *(uint4*)&Aw[lr*36 + lc + i*4] = cvt4(pa[i]);
                *(uint4*)&Bw[lr*36 + lc + i*4] = cvt4(pb[i]);
            }
        }
    }
    #pragma unroll
    for (int mf = 0; mf < 4; mf++) {
        #pragma unroll
        for (int nf = 0; nf < 4; nf++) {
            int gj = bj + wn + nf*8 + tig*2;
            float b0 = bias[gj], b1 = bias[gj + 1];
            int gi = bi + wm + mf*16 + g;
            float2 v0 = make_float2(c[mf][nf][0] + b0, c[mf][nf][1] + b1);
            *(float2*)&out[gi * EMB + gj] = v0;
            float2 v1 = make_float2(c[mf][nf][2] + b0, c[mf][nf][3] + b1);
            *(float2*)&out[(gi + 8) * EMB + gj] = v1;
        }
    }
}

// ======================= K7: flash attention (tf32 mma, K/V double-buffered) =======================
// Block: 128 query rows of one full-softmax head. 8 warps, each owns 16 rows.
// Dynamic smem: Qs[128][68] + Ks[2][64][68] + Vs[2][64][68] + Ps[128][68] = 68*512*4 = 139264 B
#define KVT (64*68)
#define FLASH_SMEM (68 * 512 * 4)
__global__ __launch_bounds__(256) void flash_tf32() {
    extern __shared__ char smraw[];
    unsigned* Qs = (unsigned*)smraw;          // [128][68]
    unsigned* Ks = Qs + 128 * 68;             // [2][64][68]
    unsigned* Vs = Ks + 2 * KVT;              // [2][64][68]
    unsigned* Ps = Vs + 2 * KVT;              // [128][68] tf32 P
    const int bh = blockIdx.x, qb = blockIdx.y;
    const int b = bh >> 3, h = 8 + (bh & 7);
    const float* qh = g_q + (b*NH + h)*SEQ*HD;
    const float* kh = g_k + (b*NH + h)*SEQ*HD;
    const float* vh = g_v + (b*NH + h)*SEQ*HD;
    const int tid = threadIdx.x, warp = tid >> 5, lane = tid & 31;
    const int g = lane >> 2, tig = lane & 3;
    const int rowA = warp * 16 + g;           // this thread's base row (also rowA+8)

    // load Q tile (128 x 64) as tf32
    {
        int r = tid >> 1, c0 = (tid & 1) * 32;
        const float* src = qh + (qb*128 + r)*HD + c0;
        unsigned* dst = Qs + r*68 + c0;
        #pragma unroll
        for (int i = 0; i < 8; i++)
            *(uint4*)(dst + i*4) = cvt4(*(const float4*)(src + i*4));
    }
    // preload K/V tile 0 and store to buffer 0
    const int kvr = tid >> 2, kvc = (tid & 3) * 16;
    float4 pk[4], pv[4];
    #pragma unroll
    for (int i = 0; i < 4; i++) {
        pk[i] = *(const float4*)(kh + kvr*HD + kvc + i*4);
        pv[i] = *(const float4*)(vh + kvr*HD + kvc + i*4);
    }
    #pragma unroll
    for (int i = 0; i < 4; i++) {
        *(uint4*)(Ks + kvr*68 + kvc + i*4) = cvt4(pk[i]);
        *(uint4*)(Vs + kvr*68 + kvc + i*4) = cvt4(pv[i]);
    }

    float o[8][4] = {};
    float mrow[2] = {-1e30f, -1e30f};
    float lrow[2] = {0.f, 0.f};

    int buf = 0;
    for (int t = 0; t < SEQ/64; t++, buf ^= 1) {
        __syncthreads();   // tile t stores visible; reads of buf^1 (iter t-1) complete
        const bool nxt = (t + 1 < SEQ/64);
        if (nxt) {
            const float* ks = kh + ((t+1)*64 + kvr)*HD + kvc;
            const float* vs = vh + ((t+1)*64 + kvr)*HD + kvc;
            #pragma unroll
            for (int i = 0; i < 4; i++) {
                pk[i] = *(const float4*)(ks + i*4);
                pv[i] = *(const float4*)(vs + i*4);
            }
        }
        const unsigned* Kb = Ks + buf*KVT;
        const unsigned* Vb = Vs + buf*KVT;

        // S = Q @ K^T for this warp's 16 rows x 64 key-cols
        float s[8][4] = {};
        #pragma unroll
        for (int k8 = 0; k8 < 8; k8++) {
            unsigned a[4];
            const unsigned* qp = Qs + rowA*68 + k8*8;
            a[0] = qp[tig]; a[1] = qp[8*68 + tig];
            a[2] = qp[tig + 4]; a[3] = qp[8*68 + tig + 4];
            #pragma unroll
            for (int nf = 0; nf < 8; nf++) {
                unsigned bfr[2];
                const unsigned* kp = Kb + (nf*8 + g)*68 + k8*8;
                bfr[0] = kp[tig]; bfr[1] = kp[tig + 4];
                mma8(s[nf], a, bfr);
            }
        }
        // online softmax (rows rowA and rowA+8)
        float mx0 = -1e30f, mx1 = -1e30f;
        #pragma unroll
        for (int nf = 0; nf < 8; nf++) {
            mx0 = fmaxf(mx0, fmaxf(s[nf][0], s[nf][1]));
            mx1 = fmaxf(mx1, fmaxf(s[nf][2], s[nf][3]));
        }
        mx0 = fmaxf(mx0, __shfl_xor_sync(0xffffffffu, mx0, 1));
        mx0 = fmaxf(mx0, __shfl_xor_sync(0xffffffffu, mx0, 2));
        mx1 = fmaxf(mx1, __shfl_xor_sync(0xffffffffu, mx1, 1));
        mx1 = fmaxf(mx1, __shfl_xor_sync(0xffffffffu, mx1, 2));
        float mn0 = fmaxf(mrow[0], mx0), mn1 = fmaxf(mrow[1], mx1);
        float sc0 = __expf(mrow[0] - mn0), sc1 = __expf(mrow[1] - mn1);
        float ls0 = 0.f, ls1 = 0.f;
        #pragma unroll
        for (int nf = 0; nf < 8; nf++) {
            float p0 = __expf(s[nf][0] - mn0);
            float p1 = __expf(s[nf][1] - mn0);
            float p2 = __expf(s[nf][2] - mn1);
            float p3 = __expf(s[nf][3] - mn1);
            ls0 += p0 + p1; ls1 += p2 + p3;
            uint2 u0; u0.x = f2tf32(p0); u0.y = f2tf32(p1);
            *(uint2*)(Ps + rowA*68 + nf*8 + tig*2) = u0;
            uint2 u1; u1.x = f2tf32(p2); u1.y = f2tf32(p3);
            *(uint2*)(Ps + (rowA + 8)*68 + nf*8 + tig*2) = u1;
        }
        ls0 += __shfl_xor_sync(0xffffffffu, ls0, 1);
        ls0 += __shfl_xor_sync(0xffffffffu, ls0, 2);
        ls1 += __shfl_xor_sync(0xffffffffu, ls1, 1);
        ls1 += __shfl_xor_sync(0xffffffffu, ls1, 2);
        lrow[0] = lrow[0]*sc0 + ls0;
        lrow[1] = lrow[1]*sc1 + ls1;
        mrow[0] = mn0; mrow[1] = mn1;
        #pragma unroll
        for (int nf = 0; nf < 8; nf++) {
            o[nf][0] *= sc0; o[nf][1] *= sc0;
            o[nf][2] *= sc1; o[nf][3] *= sc1;
        }
        __syncwarp();   // P written (own warp's rows) before fragment reload

        // out += P @ V
        #pragma unroll
        for (int k8 = 0; k8 < 8; k8++) {
            unsigned a[4];
            const unsigned* pp = Ps + rowA*68 + k8*8;
            a[0] = pp[tig];
            a[1] = pp[8*68 + tig];
            a[2] = pp[tig + 4];
            a[3] = pp[8*68 + tig + 4];
            #pragma unroll
            for (int nf = 0; nf < 8; nf++) {
                unsigned bfr[2];
                const unsigned* vp = Vb + (k8*8 + tig)*68 + nf*8 + g;
                bfr[0] = vp[0]; bfr[1] = vp[4*68];
                mma8(o[nf], a, bfr);
            }
        }
        // store prefetched tile t+1 into the other buffer
        if (nxt) {
            unsigned* Kw = Ks + (buf^1)*KVT;
            unsigned* Vw = Vs + (buf^1)*KVT;
            #pragma unroll
            for (int i = 0; i < 4; i++) {
                *(uint4*)(Kw + kvr*68 + kvc + i*4) = cvt4(pk[i]);
                *(uint4*)(Vw + kvr*68 + kvc + i*4) = cvt4(pv[i]);
            }
        }
    }
    // epilogue
    float inv0 = 1.0f / lrow[0], inv1 = 1.0f / lrow[1];
    int n0 = qb*128 + rowA;
    #pragma unroll
    for (int nf = 0; nf < 8; nf++) {
        int d = nf*8 + tig*2;
        float2 v0 = make_float2(o[nf][0]*inv0, o[nf][1]*inv0);
        *(float2*)&g_ctx[(b*SEQ + n0)*EMB + h*HD + d] = v0;
        float2 v1 = make_float2(o[nf][2]*inv1, o[nf][3]*inv1);
        *(float2*)&g_ctx[(b*SEQ + n0 + 8)*EMB + h*HD + d] = v1;
    }
}

// ======================= K2: SC = q_m @ k^T (tf32 mma, 64x64 tile) =======================
__global__ __launch_bounds__(256) void sc_tf32() {
    const int bh = blockIdx.x;               // b*8+h
    const int b = bh >> 3, h = bh & 7;
    const int n0 = blockIdx.y * 64;
    const float* qh = g_q + (b*NH + h)*SEQ*HD;
    const float* kh = g_k + (b*NH + h)*SEQ*HD;
    __shared__ unsigned Qm[64][68];          // [m][d] landmark rows (d=64, pad 68)
    __shared__ unsigned Kn[64][68];          // [n][d]
    const int tid = threadIdx.x, warp = tid >> 5, lane = tid & 31;
    const int g = lane >> 2, tig = lane & 3;
    {
        int r = tid >> 2, c = (tid & 3) * 16;
        const float* qs = qh + (r*LSTRIDE)*HD + c;
        const float* ks = kh + (n0 + r)*HD + c;
        #pragma unroll
        for (int i = 0; i < 4; i++) {
            *(uint4*)&Qm[r][c + i*4] = cvt4(*(const float4*)(qs + i*4));
            *(uint4*)&Kn[r][c + i*4] = cvt4(*(const float4*)(ks + i*4));
        }
    }
    __syncthreads();
    const int wm = (warp & 3) * 16, wn = (warp >> 2) * 32;
    float c4[4][4] = {};
    #pragma unroll
    for (int k8 = 0; k8 < 8; k8++) {
        unsigned a[4];
        a[0] = Qm[wm + g][k8*8 + tig];
        a[1] = Qm[wm + g + 8][k8*8 + tig];
        a[2] = Qm[wm + g][k8*8 + tig + 4];
        a[3] = Qm[wm + g + 8][k8*8 + tig + 4];
        #pragma unroll
        for (int nf = 0; nf < 4; nf++) {
            unsigned bb[2];
            bb[0] = Kn[wn + nf*8 + g][k8*8 + tig];
            bb[1] = Kn[wn + nf*8 + g][k8*8 + tig + 4];
            mma8(c4[nf], a, bb);
        }
    }
    float* scp = g_SC + bh*LM*SEQ;
    #pragma unroll
    for (int nf = 0; nf < 4; nf++) {
        int n = n0 + wn + nf*8 + tig*2;
        *(float2*)&scp[(wm + g)*SEQ + n]     = make_float2(c4[nf][0], c4[nf][1]);
        *(float2*)&scp[(wm + g + 8)*SEQ + n] = make_float2(c4[nf][2], c4[nf][3]);
    }
}

// ============== K3: per-row max + exp-sum of SC ==============
__global__ __launch_bounds__(256) void rowstats_kernel() {
    const int row = blockIdx.x;              // bh*64 + m
    const float* sp = g_SC + row * SEQ;
    __shared__ float red[256];
    const int tid = threadIdx.x;
    float mx = -1e30f;
    for (int n = tid; n < SEQ; n += 256) mx = fmaxf(mx, sp[n]);
    red[tid] = mx; __syncthreads();
    for (int o = 128; o > 0; o >>= 1) {
        if (tid < o) red[tid] = fmaxf(red[tid], red[tid+o]);
        __syncthreads();
    }
    const float m = red[0];
    __syncthreads();
    float s = 0.f;
    for (int n = tid; n < SEQ; n += 256) s += __expf(sp[n] - m);
    red[tid] = s; __syncthreads();
    for (int o = 128; o > 0; o >>= 1) {
        if (tid < o) red[tid] += red[tid+o];
        __syncthreads();
    }
    if (tid == 0) { g_scmax[row] = m; g_esum[row] = red[0]; }
}

// ============== K4: split-K partials of eC @ v_p (tf32 mma) ==============
__global__ __launch_bounds__(256) void ecv_tf32() {
    const int bh = blockIdx.x;
    const int b = bh >> 3, h = bh & 7;
    const int chunk = blockIdx.y;            // 0..15 -> n range of 128
    const float* vh = g_v + (b*NH + h)*SEQ*HD;
    const float* scp = g_SC + bh*LM*SEQ;
    __shared__ unsigned Et[64][68];          // [n_local][m]  exp values, tf32
    __shared__ unsigned Vs[64][68];          // [n_local][d]  tf32
    __shared__ float mx_s[64];
    const int tid = threadIdx.x, warp = tid >> 5, lane = tid & 31;
    const int g = lane >> 2, tig = lane & 3;
    const int wm = (warp & 3) * 16, wn = (warp >> 2) * 32;
    if (tid < 64) mx_s[tid] = g_scmax[bh*LM + tid];
    float acc[4][4] = {};
    for (int sub = 0; sub < 2; sub++) {
        const int nbase = chunk*128 + sub*64;
        __syncthreads();
        for (int i = tid; i < 64*16; i += 256) {
            int m = i >> 4; int s = (i & 15) * 4;
            float mxv = mx_s[m];
            float4 a = *(const float4*)&scp[m*SEQ + nbase + s];
            Et[s+0][m] = f2tf32(__expf(a.x - mxv));
            Et[s+1][m] = f2tf32(__expf(a.y - mxv));
            Et[s+2][m] = f2tf32(__expf(a.z - mxv));
            Et[s+3][m] = f2tf32(__expf(a.w - mxv));
        }
        {
            int r = tid >> 2, c = (tid & 3) * 16;
            const float* vs = vh + (nbase + r)*HD + c;
            #pragma unroll
            for (int i = 0; i < 4; i++)
                *(uint4*)&Vs[r][c + i*4] = cvt4(*(const float4*)(vs + i*4));
        }
        __syncthreads();
        #pragma unroll
        for (int k8 = 0; k8 < 8; k8++) {
            unsigned a[4];
            a[0] = Et[k8*8 + tig][wm + g];
            a[1] = Et[k8*8 + tig][wm + g + 8];
            a[2] = Et[k8*8 + tig + 4][wm + g];
            a[3] = Et[k8*8 + tig + 4][wm + g + 8];
            #pragma unroll
            for (int nf = 0; nf < 4; nf++) {
                unsigned bb[2];
                int d = wn + nf*8 + g;
                bb[0] = Vs[k8*8 + tig][d];
                bb[1] = Vs[k8*8 + tig + 4][d];
                mma8(acc[nf], a, bb);
            }
        }
    }
    float* dst = g_mid0p + (chunk*NBH + bh)*LM*HD;
    #pragma unroll
    for (int nf = 0; nf < 4; nf++) {
        int d = wn + nf*8 + tig*2;
        *(float2*)&dst[(wm + g)*HD + d]     = make_float2(acc[nf][0], acc[nf][1]);
        *(float2*)&dst[(wm + g + 8)*HD + d] = make_float2(acc[nf][2], acc[nf][3]);
    }
}

// ============== K5a: SB, eB, row/col-sum maxima ==============
__global__ __launch_bounds__(256) void sb_kernel() {
    const int bh = blockIdx.x;
    const int b = bh >> 3, h = bh & 7;
    const float* qh = g_q + (b*NH + h)*SEQ*HD;
    const float* kh = g_k + (b*NH + h)*SEQ*HD;
    __shared__ float Qt[64][64];             // [d][m], later reused as EB[m][k]
    __shared__ float Kt[64][64];             // [d][k]
    __shared__ float red[64];
    const int tid = threadIdx.x;
    for (int i = tid; i < 64*16; i += 256) {
        int r = i >> 4; int s = (i & 15) * 4;
        float4 a = *(const float4*)&qh[(r*LSTRIDE)*HD + s];
        Qt[s+0][r]=a.x; Qt[s+1][r]=a.y; Qt[s+2][r]=a.z; Qt[s+3][r]=a.w;
        float4 bb = *(const float4*)&kh[(r*LSTRIDE)*HD + s];
        Kt[s+0][r]=bb.x; Kt[s+1][r]=bb.y; Kt[s+2][r]=bb.z; Kt[s+3][r]=bb.w;
    }
    __syncthreads();
    const int tx = tid & 15, ty = tid >> 4;
    const int m0 = ty*4, k0 = tx*4;
    float acc[4][4] = {};
    #pragma unroll 8
    for (int d = 0; d < 64; d++) {
        float4 a = *(const float4*)&Qt[d][m0];
        float4 bb = *(const float4*)&Kt[d][k0];
        float Ar[4] = {a.x,a.y,a.z,a.w};
        float Br[4] = {bb.x,bb.y,bb.z,bb.w};
        #pragma unroll
        for (int ii = 0; ii < 4; ii++)
            #pragma unroll
            for (int jj = 0; jj < 4; jj++)
                acc[ii][jj] += Ar[ii]*Br[jj];
    }
    __syncthreads();                         // Qt now dead -> reuse as EB
    float (*EB)[64] = Qt;
    #pragma unroll
    for (int ii = 0; ii < 4; ii++) {
        float mx = g_scmax[bh*LM + m0 + ii];
        #pragma unroll
        for (int jj = 0; jj < 4; jj++) {
            float e = __expf(fmaxf(acc[ii][jj] - mx, -88.0f));
            EB[m0+ii][k0+jj] = e;
            g_eB[bh*LM*LM + (m0+ii)*LM + k0 + jj] = e;
        }
    }
    __syncthreads();
    if (tid < 64) {                          // row sums (reference "col")
        float s = 0.f;
        for (int k = 0; k < 64; k++) s += EB[tid][k];
        red[tid] = s;
    }
    __syncthreads();
    if (tid == 0) {
        float mx = red[0];
        for (int i = 1; i < 64; i++) mx = fmaxf(mx, red[i]);
        g_colmax[bh] = mx;
    }
    __syncthreads();
    if (tid < 64) {                          // col sums (reference "row")
        float s = 0.f;
        for (int m = 0; m < 64; m++) s += EB[m][tid];
        red[tid] = s;
    }
    __syncthreads();
    if (tid == 0) {
        float mx = red[0];
        for (int i = 1; i < 64; i++) mx = fmaxf(mx, red[i]);
        g_rowmax[bh] = mx;
    }
}

// ============== K5b: Moore-Penrose pinv + mid = pi @ (eC@v_aug) ==============
__global__ __launch_bounds__(1024) void pinv_kernel() {
    const int bh = blockIdx.x;
    const int h = bh & 7;
    __shared__ float Z[64][64];
    __shared__ float XZ[64][64];
    const int tid = threadIdx.x;
    const int i  = tid >> 4;
    const int j0 = (tid & 15) * 4;
    const float* Xg = g_eB + bh*LM*LM;
    float* Tg = g_T + bh*LM*LM;
    float* Ug = g_U + bh*LM*LM;

    // denom: max over batch per head
    const float colM = fmaxf(g_colmax[h], g_colmax[8 + h]);
    const float rowM = fmaxf(g_rowmax[h], g_rowmax[8 + h]);
    const float rden = 1.0f / (colM * rowM);

    // z = x^T / denom
    #pragma unroll
    for (int jj = 0; jj < 4; jj++)
        Z[i][j0+jj] = Xg[(j0+jj)*64 + i] * rden;
    __syncthreads();

    for (int it = 0; it < 6; it++) {
        {
            float a0=0,a1=0,a2=0,a3=0;
            for (int k = 0; k < 64; k++) {
                float a = Xg[i*64 + k];
                float4 bz = *(const float4*)&Z[k][j0];
                a0 += a*bz.x; a1 += a*bz.y; a2 += a*bz.z; a3 += a*bz.w;
            }
            XZ[i][j0+0]=a0; XZ[i][j0+1]=a1; XZ[i][j0+2]=a2; XZ[i][j0+3]=a3;
        }
        __syncthreads();
        {
            float a0=0,a1=0,a2=0,a3=0;
            for (int k = 0; k < 64; k++) {
                float a = XZ[i][k];
                float4 bz = *(const float4*)&XZ[k][j0];
                a0 += a*bz.x; a1 += a*bz.y; a2 += a*bz.z; a3 += a*bz.w;
            }
            float4 xz4 = *(const float4*)&XZ[i][j0];
            float4 o = make_float4(7.f*xz4.x - a0, 7.f*xz4.y - a1,
                                   7.f*xz4.z - a2, 7.f*xz4.w - a3);
            *(float4*)&Tg[i*64 + j0] = o;
        }
        __syncthreads();
        {
            float a0=0,a1=0,a2=0,a3=0;
            for (int k = 0; k < 64; k++) {
                float a = XZ[i][k];
                float4 bz = *(const float4*)&Tg[k*64 + j0];
                a0 += a*bz.x; a1 += a*bz.y; a2 += a*bz.z; a3 += a*bz.w;
            }
            float4 xz4 = *(const float4*)&XZ[i][j0];
            float4 o = make_float4(15.f*xz4.x - a0, 15.f*xz4.y - a1,
                                   15.f*xz4.z - a2, 15.f*xz4.w - a3);
            *(float4*)&Ug[i*64 + j0] = o;
        }
        __syncthreads();
        {
            float a0=0,a1=0,a2=0,a3=0;
            for (int k = 0; k < 64; k++) {
                float a = Z[i][k];
                float4 bz = *(const float4*)&Ug[k*64 + j0];
                a0 += a*bz.x; a1 += a*bz.y; a2 += a*bz.z; a3 += a*bz.w;
            }
            float4 z4 = *(const float4*)&Z[i][j0];
            float4 o = make_float4(0.25f*(13.f*z4.x - a0), 0.25f*(13.f*z4.y - a1),
                                   0.25f*(13.f*z4.z - a2), 0.25f*(13.f*z4.w - a3));
            *(float4*)&Tg[i*64 + j0] = o;
        }
        __syncthreads();
        *(float4*)&Z[i][j0] = *(const float4*)&Tg[i*64 + j0];
        __syncthreads();
    }

    {
        float4 s = make_float4(0,0,0,0);
        for (int c = 0; c < NCHUNK; c++) {
            float4 p = *(const float4*)&g_mid0p[(c*NBH + bh)*LM*HD + i*64 + j0];
            s.x += p.x; s.y += p.y; s.z += p.z; s.w += p.w;
        }
        *(float4*)&XZ[i][j0] = s;
    }
    __syncthreads();
    {
        float a0=0,a1=0,a2=0,a3=0;
        for (int k = 0; k < 64; k++) {
            float a = Z[i][k];
            float4 bz = *(const float4*)&XZ[k][j0];
            a0 += a*bz.x; a1 += a*bz.y; a2 += a*bz.z; a3 += a*bz.w;
        }
        float* mp = g_mid + bh*LM*(HD+1) + i*(HD+1) + j0;
        mp[0]=a0; mp[1]=a1; mp[2]=a2; mp[3]=a3;
    }
    if (tid < 64) {
        float s = 0.f;
        for (int k = 0; k < 64; k++) s += Z[tid][k] * g_esum[bh*LM + k];
        g_mid[bh*LM*(HD+1) + tid*(HD+1) + 64] = s;
    }
}

// ============== K6: out_p = softmax-ish(q_p@k_m^T) @ mid, divide ==============
__global__ __launch_bounds__(256) void nystrom_out_kernel() {
    const int bh = blockIdx.x;
    const int b = bh >> 3, h = bh & 7;
    const int qb = blockIdx.y;               // 0..31
    const float* qh = g_q + (b*NH + h)*SEQ*HD;
    __shared__ float A1[64][64];             // Qt[d][r] then P[r][k]
    __shared__ float A2[64][64];             // Kmt[d][k] then Ms[k][j]
    __shared__ float rm[64], den[64], mcol[64];
    const int tid = threadIdx.x;
    for (int i = tid; i < 64*16; i += 256) {
        int r = i >> 4; int s = (i & 15) * 4;
        float4 a = *(const float4*)&qh[(qb*64 + r)*HD + s];
        A1[s+0][r]=a.x; A1[s+1][r]=a.y; A1[s+2][r]=a.z; A1[s+3][r]=a.w;
        const float* kh = g_k + (b*NH + h)*SEQ*HD;
        float4 bb = *(const float4*)&kh[(r*LSTRIDE)*HD + s];
        A2[s+0][r]=bb.x; A2[s+1][r]=bb.y; A2[s+2][r]=bb.z; A2[s+3][r]=bb.w;
    }
    __syncthreads();
    const int tx = tid & 15, ty = tid >> 4;
    const int r0 = ty*4, k0 = tx*4;
    float acc[4][4] = {};
    #pragma unroll 8
    for (int d = 0; d < 64; d++) {
        float4 a = *(const float4*)&A1[d][r0];
        float4 bb = *(const float4*)&A2[d][k0];
        float Ar[4] = {a.x,a.y,a.z,a.w};
        float Br[4] = {bb.x,bb.y,bb.z,bb.w};
        #pragma unroll
        for (int ii = 0; ii < 4; ii++)
            #pragma unroll
            for (int jj = 0; jj < 4; jj++)
                acc[ii][jj] += Ar[ii]*Br[jj];
    }
    __syncthreads();
    #pragma unroll
    for (int ii = 0; ii < 4; ii++)
        #pragma unroll
        for (int jj = 0; jj < 4; jj++)
            A1[r0+ii][k0+jj] = acc[ii][jj];
    const float* mp = g_mid + bh*LM*(HD+1);
    for (int i = tid; i < 4096; i += 256) {
        int k = i >> 6, j = i & 63;
        A2[k][j] = mp[k*(HD+1) + j];
    }
    if (tid < 64) mcol[tid] = mp[tid*(HD+1) + 64];
    __syncthreads();
    if (tid < 64) {
        float mx = -1e30f;
        for (int k = 0; k < 64; k++) mx = fmaxf(mx, A1[tid][k]);
        rm[tid] = mx;
    }
    __syncthreads();
    for (int i = tid; i < 4096; i += 256) {
        int r = i >> 6, k = i & 63;
        A1[r][k] = __expf(A1[r][k] - rm[r]);
    }
    __syncthreads();
    if (tid < 64) {
        float s = 0.f;
        for (int k = 0; k < 64; k++) s += A1[tid][k] * mcol[k];
        den[tid] = s;
    }
    __syncthreads();
    float o[4][4] = {};
    #pragma unroll 8
    for (int k = 0; k < 64; k++) {
        float4 bb = *(const float4*)&A2[k][k0];
        float Br[4] = {bb.x,bb.y,bb.z,bb.w};
        #pragma unroll
        for (int ii = 0; ii < 4; ii++) {
            float a = A1[r0+ii][k];
            #pragma unroll
            for (int jj = 0; jj < 4; jj++)
                o[ii][jj] += a * Br[jj];
        }
    }
    #pragma unroll
    for (int ii = 0; ii < 4; ii++) {
        float inv = 1.0f / fmaxf(den[r0+ii], 1e-8f);
        int n = qb*64 + r0 + ii;
        float4 v = make_float4(o[ii][0]*inv, o[ii][1]*inv, o[ii][2]*inv, o[ii][3]*inv);
        *(float4*)&g_ctx[(b*SEQ + n)*EMB + h*HD + k0] = v;
    }
}

// =================================================================================
extern "C" void kernel_launch(void* const* d_in, const int* in_sizes, int n_in,
                              void* d_out, int out_size) {
    (void)in_sizes; (void)n_in; (void)out_size;
    const float* x      = (const float*)d_in[0];
    const float* qkv_w  = (const float*)d_in[1];
    const float* qkv_b  = (const float*)d_in[2];
    const float* proj_w = (const float*)d_in[3];
    const float* proj_b = (const float*)d_in[4];
    float* out = (float*)d_out;

    cudaFuncSetAttribute(flash_tf32, cudaFuncAttributeMaxDynamicSharedMemorySize, FLASH_SMEM);
    cudaFuncSetAttribute(qkv_gemm_tf32, cudaFuncAttributeMaxDynamicSharedMemorySize, GEMM_SMEM);
    cudaFuncSetAttribute(proj_gemm_tf32, cudaFuncAttributeMaxDynamicSharedMemorySize, GEMM_SMEM);

    qkv_gemm_tf32<<<dim3(24, 32), 256, GEMM_SMEM>>>(x, qkv_w, qkv_b);
    sc_tf32<<<dim3(NBH, SEQ/64), 256>>>();
    rowstats_kernel<<<NBH*LM, 256>>>();
    ecv_tf32<<<dim3(NBH, NCHUNK), 256>>>();
    sb_kernel<<<NBH, 256>>>();
    pinv_kernel<<<NBH, 1024>>>();
    nystrom_out_kernel<<<dim3(NBH, SEQ/64), 256>>>();
    flash_tf32<<<dim3(NBH, SEQ/128), 256, FLASH_SMEM>>>();
    proj_gemm_tf32<<<dim3(8, 32), 256, GEMM_SMEM>>>(proj_w, proj_b, out);
}

// round 12
// speedup vs baseline: 1.0458x; 1.0458x over previous
#include <cuda_runtime.h>
#include <math.h>

#define BATCH 2
#define SEQ   2048
#define EMB   1024
#define NH    16
#define HD    64
#define PHH   8      // pnp heads
#define LM    64     // landmarks
#define NBH   16     // BATCH * PHH
#define QSCALE 0.125f
#define LSTRIDE 32   // SEQ / LM
#define NCHUNK 16    // ecv split-K chunks

// ---------------- scratch (device globals; no runtime allocation) ----------------
__device__ float g_q[BATCH*NH*SEQ*HD];
__device__ float g_k[BATCH*NH*SEQ*HD];
__device__ float g_v[BATCH*NH*SEQ*HD];
__device__ float g_SC[NBH*LM*SEQ];          // q_m @ k^T per pnp head
__device__ float g_scmax[NBH*LM];
__device__ float g_esum[NBH*LM];            // rowsum of eC
__device__ float g_mid0p[NCHUNK*NBH*LM*HD]; // split-K partials of eC @ v_p
__device__ float g_eB[NBH*LM*LM];
__device__ float g_T[NBH*LM*LM];            // pinv temp
__device__ float g_U[NBH*LM*LM];            // pinv temp
__device__ float g_colmax[NBH];
__device__ float g_rowmax[NBH];
__device__ float g_mid[NBH*LM*(HD+1)];      // pi @ (eC @ v_aug), 65 cols
__device__ float g_ctx[BATCH*SEQ*EMB];

// ---------------- tf32 mma helpers ----------------
__device__ __forceinline__ unsigned f2tf32(float x) {
    unsigned r;
    asm("cvt.rna.tf32.f32 %0, %1;" : "=r"(r) : "f"(x));
    return r;
}
__device__ __forceinline__ void mma8(float* c, const unsigned* a, const unsigned* b) {
    asm volatile(
        "mma.sync.aligned.m16n8k8.row.col.f32.tf32.tf32.f32 "
        "{%0,%1,%2,%3},{%4,%5,%6,%7},{%8,%9},{%0,%1,%2,%3};\n"
        : "+f"(c[0]), "+f"(c[1]), "+f"(c[2]), "+f"(c[3])
        : "r"(a[0]), "r"(a[1]), "r"(a[2]), "r"(a[3]), "r"(b[0]), "r"(b[1]));
}
__device__ __forceinline__ uint4 cvt4(float4 v) {
    uint4 u;
    u.x = f2tf32(v.x); u.y = f2tf32(v.y); u.z = f2tf32(v.z); u.w = f2tf32(v.w);
    return u;
}

// ======================= K1: QKV GEMM (tf32, 128x128x32 tiles) =======================
__global__ __launch_bounds__(256) void qkv_gemm_tf32(const float* __restrict__ X,
                                                     const float* __restrict__ W,
                                                     const float* __restrict__ bias) {
    __shared__ unsigned As[128][36];   // [m][k], k-tile 32, pad 36
    __shared__ unsigned Bs[128][36];   // [n][k]
    const int bi = blockIdx.y * 128;
    const int bj = blockIdx.x * 128;
    const int tid = threadIdx.x, warp = tid >> 5, lane = tid & 31;
    const int g = lane >> 2, tig = lane & 3;
    const int wm = (warp & 1) * 64, wn = (warp >> 1) * 32;
    float c[4][4][4] = {};
    const int lr = tid >> 1, lc = (tid & 1) * 16;
    const float* ax = X + (bi + lr) * EMB + lc;
    const float* bx = W + (bj + lr) * EMB + lc;
    float4 pa[4], pb[4];
    #pragma unroll
    for (int i = 0; i < 4; i++) {
        pa[i] = *(const float4*)(ax + i*4);
        pb[i] = *(const float4*)(bx + i*4);
    }
    for (int k0 = 0; k0 < EMB; k0 += 32) {
        #pragma unroll
        for (int i = 0; i < 4; i++) {
            *(uint4*)&As[lr][lc + i*4] = cvt4(pa[i]);
            *(uint4*)&Bs[lr][lc + i*4] = cvt4(pb[i]);
        }
        __syncthreads();
        if (k0 < EMB - 32) {
            #pragma unroll
            for (int i = 0; i < 4; i++) {
                pa[i] = *(const float4*)(ax + k0 + 32 + i*4);
                pb[i] = *(const float4*)(bx + k0 + 32 + i*4);
            }
        }
        #pragma unroll
        for (int ks = 0; ks < 4; ks++) {
            unsigned a[4][4], bb[4][2];
            #pragma unroll
            for (int mf = 0; mf < 4; mf++) {
                const unsigned* p = &As[wm + mf*16 + g][ks*8 + tig];
                a[mf][0] = p[0];
                a[mf][1] = p[8*36];
                a[mf][2] = p[4];
                a[mf][3] = p[8*36 + 4];
            }
            #pragma unroll
            for (int nf = 0; nf < 4; nf++) {
                const unsigned* p = &Bs[wn + nf*8 + g][ks*8 + tig];
                bb[nf][0] = p[0];
                bb[nf][1] = p[4];
            }
            #pragma unroll
            for (int mf = 0; mf < 4; mf++)
                #pragma unroll
                for (int nf = 0; nf < 4; nf++)
                    mma8(c[mf][nf], a[mf], bb[nf]);
        }
        __syncthreads();
    }
    // epilogue: scatter into q/k/v [B][H][N][D], scale q
    #pragma unroll
    for (int mf = 0; mf < 4; mf++) {
        #pragma unroll
        for (int nf = 0; nf < 4; nf++) {
            int gj = bj + wn + nf*8 + tig*2;
            int s  = gj >> 10;
            int hh = (gj >> 6) & 15;
            int dd = gj & 63;
            float b0 = bias[gj], b1 = bias[gj + 1];
            float* dst = (s == 0) ? g_q : (s == 1) ? g_k : g_v;
            float mul = (s == 0) ? QSCALE : 1.0f;
            int gi = bi + wm + mf*16 + g;
            int bb2 = gi >> 11, n = gi & 2047;
            float2 v0 = make_float2((c[mf][nf][0] + b0) * mul, (c[mf][nf][1] + b1) * mul);
            *(float2*)&dst[((bb2*NH + hh)*SEQ + n)*HD + dd] = v0;
            float2 v1 = make_float2((c[mf][nf][2] + b0) * mul, (c[mf][nf][3] + b1) * mul);
            *(float2*)&dst[((bb2*NH + hh)*SEQ + n + 8)*HD + dd] = v1;
        }
    }
}

// ======================= K8: output projection GEMM (tf32, k-tile 32) =======================
__global__ __launch_bounds__(256) void proj_gemm_tf32(const float* __restrict__ W,
                                                      const float* __restrict__ bias,
                                                      float* __restrict__ out) {
    __shared__ unsigned As[128][36];
    __shared__ unsigned Bs[128][36];
    const int bi = blockIdx.y * 128;
    const int bj = blockIdx.x * 128;
    const int tid = threadIdx.x, warp = tid >> 5, lane = tid & 31;
    const int g = lane >> 2, tig = lane & 3;
    const int wm = (warp & 1) * 64, wn = (warp >> 1) * 32;
    float c[4][4][4] = {};
    const int lr = tid >> 1, lc = (tid & 1) * 16;
    const float* ax = g_ctx + (bi + lr) * EMB + lc;
    const float* bx = W + (bj + lr) * EMB + lc;
    float4 pa[4], pb[4];
    #pragma unroll
    for (int i = 0; i < 4; i++) {
        pa[i] = *(const float4*)(ax + i*4);
        pb[i] = *(const float4*)(bx + i*4);
    }
    for (int k0 = 0; k0 < EMB; k0 += 32) {
        #pragma unroll
        for (int i = 0; i < 4; i++) {
            *(uint4*)&As[lr][lc + i*4] = cvt4(pa[i]);
            *(uint4*)&Bs[lr][lc + i*4] = cvt4(pb[i]);
        }
        __syncthreads();
        if (k0 < EMB - 32) {
            #pragma unroll
            for (int i = 0; i < 4; i++) {
                pa[i] = *(const float4*)(ax + k0 + 32 + i*4);
                pb[i] = *(const float4*)(bx + k0 + 32 + i*4);
            }
        }
        #pragma unroll
        for (int ks = 0; ks < 4; ks++) {
            unsigned a[4][4], bb[4][2];
            #pragma unroll
            for (int mf = 0; mf < 4; mf++) {
                const unsigned* p = &As[wm + mf*16 + g][ks*8 + tig];
                a[mf][0] = p[0];
                a[mf][1] = p[8*36];
                a[mf][2] = p[4];
                a[mf][3] = p[8*36 + 4];
            }
            #pragma unroll
            for (int nf = 0; nf < 4; nf++) {
                const unsigned* p = &Bs[wn + nf*8 + g][ks*8 + tig];
                bb[nf][0] = p[0];
                bb[nf][1] = p[4];
            }
            #pragma unroll
            for (int mf = 0; mf < 4; mf++)
                #pragma unroll
                for (int nf = 0; nf < 4; nf++)
                    mma8(c[mf][nf], a[mf], bb[nf]);
        }
        __syncthreads();
    }
    #pragma unroll
    for (int mf = 0; mf < 4; mf++) {
        #pragma unroll
        for (int nf = 0; nf < 4; nf++) {
            int gj = bj + wn + nf*8 + tig*2;
            float b0 = bias[gj], b1 = bias[gj + 1];
            int gi = bi + wm + mf*16 + g;
            float2 v0 = make_float2(c[mf][nf][0] + b0, c[mf][nf][1] + b1);
            *(float2*)&out[gi * EMB + gj] = v0;
            float2 v1 = make_float2(c[mf][nf][2] + b0, c[mf][nf][3] + b1);
            *(float2*)&out[(gi + 8) * EMB + gj] = v1;
        }
    }
}

// ======================= K7: flash attention (tf32 mma, single-buffer K/V reg prefetch) =======================
// Block: 128 query rows of one full-softmax head. 8 warps, each owns 16 rows.
// Dynamic smem: Qs[128][68] + Ks[64][68] + Vs[64][68] + Ps[128][68] = 104448 B (2 CTAs/SM)
#define FLASH_SMEM (68 * 384 * 4)
__global__ __launch_bounds__(256, 2) void flash_tf32() {
    extern __shared__ char smraw[];
    unsigned* Qs = (unsigned*)smraw;          // [128][68]
    unsigned* Ks = Qs + 128 * 68;             // [64][68]
    unsigned* Vs = Ks + 64 * 68;              // [64][68]
    unsigned* Ps = Vs + 64 * 68;              // [128][68] tf32 P
    const int bh = blockIdx.x, qb = blockIdx.y;
    const int b = bh >> 3, h = 8 + (bh & 7);
    const float* qh = g_q + (b*NH + h)*SEQ*HD;
    const float* kh = g_k + (b*NH + h)*SEQ*HD;
    const float* vh = g_v + (b*NH + h)*SEQ*HD;
    const int tid = threadIdx.x, warp = tid >> 5, lane = tid & 31;
    const int g = lane >> 2, tig = lane & 3;
    const int rowA = warp * 16 + g;           // this thread's base row (also rowA+8)

    // load Q tile (128 x 64) as tf32
    {
        int r = tid >> 1, c0 = (tid & 1) * 32;
        const float* src = qh + (qb*128 + r)*HD + c0;
        unsigned* dst = Qs + r*68 + c0;
        #pragma unroll
        for (int i = 0; i < 8; i++)
            *(uint4*)(dst + i*4) = cvt4(*(const float4*)(src + i*4));
    }
    // prefetch K/V tile 0 into registers (tf32-converted)
    const int kvr = tid >> 2, kvc = (tid & 3) * 16;
    uint4 qk[4], qv[4];
    #pragma unroll
    for (int i = 0; i < 4; i++) {
        qk[i] = cvt4(*(const float4*)(kh + kvr*HD + kvc + i*4));
        qv[i] = cvt4(*(const float4*)(vh + kvr*HD + kvc + i*4));
    }

    float o[8][4] = {};
    float mrow[2] = {-1e30f, -1e30f};
    float lrow[2] = {0.f, 0.f};

    for (int t = 0; t < SEQ/64; t++) {
        __syncthreads();   // reads of tile t-1 done (t>0); Q store pre-loop ordered too
        // store prefetched tile t into the single K/V buffer
        #pragma unroll
        for (int i = 0; i < 4; i++) {
            *(uint4*)(Ks + kvr*68 + kvc + i*4) = qk[i];
            *(uint4*)(Vs + kvr*68 + kvc + i*4) = qv[i];
        }
        __syncthreads();   // tile t visible
        // issue LDG for tile t+1; latency hides under both mma phases below
        if (t + 1 < SEQ/64) {
            const float* ks = kh + ((t+1)*64 + kvr)*HD + kvc;
            const float* vs = vh + ((t+1)*64 + kvr)*HD + kvc;
            #pragma unroll
            for (int i = 0; i < 4; i++) {
                qk[i] = cvt4(*(const float4*)(ks + i*4));
                qv[i] = cvt4(*(const float4*)(vs + i*4));
            }
        }

        // S = Q @ K^T for this warp's 16 rows x 64 key-cols
        float s[8][4] = {};
        #pragma unroll
        for (int k8 = 0; k8 < 8; k8++) {
            unsigned a[4];
            const unsigned* qp = Qs + rowA*68 + k8*8;
            a[0] = qp[tig]; a[1] = qp[8*68 + tig];
            a[2] = qp[tig + 4]; a[3] = qp[8*68 + tig + 4];
            #pragma unroll
            for (int nf = 0; nf < 8; nf++) {
                unsigned bfr[2];
                const unsigned* kp = Ks + (nf*8 + g)*68 + k8*8;
                bfr[0] = kp[tig]; bfr[1] = kp[tig + 4];
                mma8(s[nf], a, bfr);
            }
        }
        // online softmax (rows rowA and rowA+8)
        float mx0 = -1e30f, mx1 = -1e30f;
        #pragma unroll
        for (int nf = 0; nf < 8; nf++) {
            mx0 = fmaxf(mx0, fmaxf(s[nf][0], s[nf][1]));
            mx1 = fmaxf(mx1, fmaxf(s[nf][2], s[nf][3]));
        }
        mx0 = fmaxf(mx0, __shfl_xor_sync(0xffffffffu, mx0, 1));
        mx0 = fmaxf(mx0, __shfl_xor_sync(0xffffffffu, mx0, 2));
        mx1 = fmaxf(mx1, __shfl_xor_sync(0xffffffffu, mx1, 1));
        mx1 = fmaxf(mx1, __shfl_xor_sync(0xffffffffu, mx1, 2));
        float mn0 = fmaxf(mrow[0], mx0), mn1 = fmaxf(mrow[1], mx1);
        float sc0 = __expf(mrow[0] - mn0), sc1 = __expf(mrow[1] - mn1);
        float ls0 = 0.f, ls1 = 0.f;
        #pragma unroll
        for (int nf = 0; nf < 8; nf++) {
            float p0 = __expf(s[nf][0] - mn0);
            float p1 = __expf(s[nf][1] - mn0);
            float p2 = __expf(s[nf][2] - mn1);
            float p3 = __expf(s[nf][3] - mn1);
            ls0 += p0 + p1; ls1 += p2 + p3;
            uint2 u0; u0.x = f2tf32(p0); u0.y = f2tf32(p1);
            *(uint2*)(Ps + rowA*68 + nf*8 + tig*2) = u0;
            uint2 u1; u1.x = f2tf32(p2); u1.y = f2tf32(p3);
            *(uint2*)(Ps + (rowA + 8)*68 + nf*8 + tig*2) = u1;
        }
        ls0 += __shfl_xor_sync(0xffffffffu, ls0, 1);
        ls0 += __shfl_xor_sync(0xffffffffu, ls0, 2);
        ls1 += __shfl_xor_sync(0xffffffffu, ls1, 1);
        ls1 += __shfl_xor_sync(0xffffffffu, ls1, 2);
        lrow[0] = lrow[0]*sc0 + ls0;
        lrow[1] = lrow[1]*sc1 + ls1;
        mrow[0] = mn0; mrow[1] = mn1;
        #pragma unroll
        for (int nf = 0; nf < 8; nf++) {
            o[nf][0] *= sc0; o[nf][1] *= sc0;
            o[nf][2] *= sc1; o[nf][3] *= sc1;
        }
        __syncwarp();   // P written (own warp's rows) before fragment reload

        // out += P @ V
        #pragma unroll
        for (int k8 = 0; k8 < 8; k8++) {
            unsigned a[4];
            const unsigned* pp = Ps + rowA*68 + k8*8;
            a[0] = pp[tig];
            a[1] = pp[8*68 + tig];
            a[2] = pp[tig + 4];
            a[3] = pp[8*68 + tig + 4];
            #pragma unroll
            for (int nf = 0; nf < 8; nf++) {
                unsigned bfr[2];
                const unsigned* vp = Vs + (k8*8 + tig)*68 + nf*8 + g;
                bfr[0] = vp[0]; bfr[1] = vp[4*68];
                mma8(o[nf], a, bfr);
            }
        }
    }
    // epilogue
    float inv0 = 1.0f / lrow[0], inv1 = 1.0f / lrow[1];
    int n0 = qb*128 + rowA;
    #pragma unroll
    for (int nf = 0; nf < 8; nf++) {
        int d = nf*8 + tig*2;
        float2 v0 = make_float2(o[nf][0]*inv0, o[nf][1]*inv0);
        *(float2*)&g_ctx[(b*SEQ + n0)*EMB + h*HD + d] = v0;
        float2 v1 = make_float2(o[nf][2]*inv1, o[nf][3]*inv1);
        *(float2*)&g_ctx[(b*SEQ + n0 + 8)*EMB + h*HD + d] = v1;
    }
}

// ======================= K2: SC = q_m @ k^T (tf32 mma, 64x64 tile) =======================
__global__ __launch_bounds__(256) void sc_tf32() {
    const int bh = blockIdx.x;               // b*8+h
    const int b = bh >> 3, h = bh & 7;
    const int n0 = blockIdx.y * 64;
    const float* qh = g_q + (b*NH + h)*SEQ*HD;
    const float* kh = g_k + (b*NH + h)*SEQ*HD;
    __shared__ unsigned Qm[64][68];          // [m][d] landmark rows (d=64, pad 68)
    __shared__ unsigned Kn[64][68];          // [n][d]
    const int tid = threadIdx.x, warp = tid >> 5, lane = tid & 31;
    const int g = lane >> 2, tig = lane & 3;
    {
        int r = tid >> 2, c = (tid & 3) * 16;
        const float* qs = qh + (r*LSTRIDE)*HD + c;
        const float* ks = kh + (n0 + r)*HD + c;
        #pragma unroll
        for (int i = 0; i < 4; i++) {
            *(uint4*)&Qm[r][c + i*4] = cvt4(*(const float4*)(qs + i*4));
            *(uint4*)&Kn[r][c + i*4] = cvt4(*(const float4*)(ks + i*4));
        }
    }
    __syncthreads();
    const int wm = (warp & 3) * 16, wn = (warp >> 2) * 32;
    float c4[4][4] = {};
    #pragma unroll
    for (int k8 = 0; k8 < 8; k8++) {
        unsigned a[4];
        a[0] = Qm[wm + g][k8*8 + tig];
        a[1] = Qm[wm + g + 8][k8*8 + tig];
        a[2] = Qm[wm + g][k8*8 + tig + 4];
        a[3] = Qm[wm + g + 8][k8*8 + tig + 4];
        #pragma unroll
        for (int nf = 0; nf < 4; nf++) {
            unsigned bb[2];
            bb[0] = Kn[wn + nf*8 + g][k8*8 + tig];
            bb[1] = Kn[wn + nf*8 + g][k8*8 + tig + 4];
            mma8(c4[nf], a, bb);
        }
    }
    float* scp = g_SC + bh*LM*SEQ;
    #pragma unroll
    for (int nf = 0; nf < 4; nf++) {
        int n = n0 + wn + nf*8 + tig*2;
        *(float2*)&scp[(wm + g)*SEQ + n]     = make_float2(c4[nf][0], c4[nf][1]);
        *(float2*)&scp[(wm + g + 8)*SEQ + n] = make_float2(c4[nf][2], c4[nf][3]);
    }
}

// ============== K3: per-row max + exp-sum of SC ==============
__global__ __launch_bounds__(256) void rowstats_kernel() {
    const int row = blockIdx.x;              // bh*64 + m
    const float* sp = g_SC + row * SEQ;
    __shared__ float red[256];
    const int tid = threadIdx.x;
    float mx = -1e30f;
    for (int n = tid; n < SEQ; n += 256) mx = fmaxf(mx, sp[n]);
    red[tid] = mx; __syncthreads();
    for (int o = 128; o > 0; o >>= 1) {
        if (tid < o) red[tid] = fmaxf(red[tid], red[tid+o]);
        __syncthreads();
    }
    const float m = red[0];
    __syncthreads();
    float s = 0.f;
    for (int n = tid; n < SEQ; n += 256) s += __expf(sp[n] - m);
    red[tid] = s; __syncthreads();
    for (int o = 128; o > 0; o >>= 1) {
        if (tid < o) red[tid] += red[tid+o];
        __syncthreads();
    }
    if (tid == 0) { g_scmax[row] = m; g_esum[row] = red[0]; }
}

// ============== K4: split-K partials of eC @ v_p (tf32 mma) ==============
__global__ __launch_bounds__(256) void ecv_tf32() {
    const int bh = blockIdx.x;
    const int b = bh >> 3, h = bh & 7;
    const int chunk = blockIdx.y;            // 0..15 -> n range of 128
    const float* vh = g_v + (b*NH + h)*SEQ*HD;
    const float* scp = g_SC + bh*LM*SEQ;
    __shared__ unsigned Et[64][68];          // [n_local][m]  exp values, tf32
    __shared__ unsigned Vs[64][68];          // [n_local][d]  tf32
    __shared__ float mx_s[64];
    const int tid = threadIdx.x, warp = tid >> 5, lane = tid & 31;
    const int g = lane >> 2, tig = lane & 3;
    const int wm = (warp & 3) * 16, wn = (warp >> 2) * 32;
    if (tid < 64) mx_s[tid] = g_scmax[bh*LM + tid];
    float acc[4][4] = {};
    for (int sub = 0; sub < 2; sub++) {
        const int nbase = chunk*128 + sub*64;
        __syncthreads();
        for (int i = tid; i < 64*16; i += 256) {
            int m = i >> 4; int s = (i & 15) * 4;
            float mxv = mx_s[m];
            float4 a = *(const float4*)&scp[m*SEQ + nbase + s];
            Et[s+0][m] = f2tf32(__expf(a.x - mxv));
            Et[s+1][m] = f2tf32(__expf(a.y - mxv));
            Et[s+2][m] = f2tf32(__expf(a.z - mxv));
            Et[s+3][m] = f2tf32(__expf(a.w - mxv));
        }
        {
            int r = tid >> 2, c = (tid & 3) * 16;
            const float* vs = vh + (nbase + r)*HD + c;
            #pragma unroll
            for (int i = 0; i < 4; i++)
                *(uint4*)&Vs[r][c + i*4] = cvt4(*(const float4*)(vs + i*4));
        }
        __syncthreads();
        #pragma unroll
        for (int k8 = 0; k8 < 8; k8++) {
            unsigned a[4];
            a[0] = Et[k8*8 + tig][wm + g];
            a[1] = Et[k8*8 + tig][wm + g + 8];
            a[2] = Et[k8*8 + tig + 4][wm + g];
            a[3] = Et[k8*8 + tig + 4][wm + g + 8];
            #pragma unroll
            for (int nf = 0; nf < 4; nf++) {
                unsigned bb[2];
                int d = wn + nf*8 + g;
                bb[0] = Vs[k8*8 + tig][d];
                bb[1] = Vs[k8*8 + tig + 4][d];
                mma8(acc[nf], a, bb);
            }
        }
    }
    float* dst = g_mid0p + (chunk*NBH + bh)*LM*HD;
    #pragma unroll
    for (int nf = 0; nf < 4; nf++) {
        int d = wn + nf*8 + tig*2;
        *(float2*)&dst[(wm + g)*HD + d]     = make_float2(acc[nf][0], acc[nf][1]);
        *(float2*)&dst[(wm + g + 8)*HD + d] = make_float2(acc[nf][2], acc[nf][3]);
    }
}

// ============== K5a: SB, eB, row/col-sum maxima ==============
__global__ __launch_bounds__(256) void sb_kernel() {
    const int bh = blockIdx.x;
    const int b = bh >> 3, h = bh & 7;
    const float* qh = g_q + (b*NH + h)*SEQ*HD;
    const float* kh = g_k + (b*NH + h)*SEQ*HD;
    __shared__ float Qt[64][64];             // [d][m], later reused as EB[m][k]
    __shared__ float Kt[64][64];             // [d][k]
    __shared__ float red[64];
    const int tid = threadIdx.x;
    for (int i = tid; i < 64*16; i += 256) {
        int r = i >> 4; int s = (i & 15) * 4;
        float4 a = *(const float4*)&qh[(r*LSTRIDE)*HD + s];
        Qt[s+0][r]=a.x; Qt[s+1][r]=a.y; Qt[s+2][r]=a.z; Qt[s+3][r]=a.w;
        float4 bb = *(const float4*)&kh[(r*LSTRIDE)*HD + s];
        Kt[s+0][r]=bb.x; Kt[s+1][r]=bb.y; Kt[s+2][r]=bb.z; Kt[s+3][r]=bb.w;
    }
    __syncthreads();
    const int tx = tid & 15, ty = tid >> 4;
    const int m0 = ty*4, k0 = tx*4;
    float acc[4][4] = {};
    #pragma unroll 8
    for (int d = 0; d < 64; d++) {
        float4 a = *(const float4*)&Qt[d][m0];
        float4 bb = *(const float4*)&Kt[d][k0];
        float Ar[4] = {a.x,a.y,a.z,a.w};
        float Br[4] = {bb.x,bb.y,bb.z,bb.w};
        #pragma unroll
        for (int ii = 0; ii < 4; ii++)
            #pragma unroll
            for (int jj = 0; jj < 4; jj++)
                acc[ii][jj] += Ar[ii]*Br[jj];
    }
    __syncthreads();                         // Qt now dead -> reuse as EB
    float (*EB)[64] = Qt;
    #pragma unroll
    for (int ii = 0; ii < 4; ii++) {
        float mx = g_scmax[bh*LM + m0 + ii];
        #pragma unroll
        for (int jj = 0; jj < 4; jj++) {
            float e = __expf(fmaxf(acc[ii][jj] - mx, -88.0f));
            EB[m0+ii][k0+jj] = e;
            g_eB[bh*LM*LM + (m0+ii)*LM + k0 + jj] = e;
        }
    }
    __syncthreads();
    if (tid < 64) {                          // row sums (reference "col")
        float s = 0.f;
        for (int k = 0; k < 64; k++) s += EB[tid][k];
        red[tid] = s;
    }
    __syncthreads();
    if (tid == 0) {
        float mx = red[0];
        for (int i = 1; i < 64; i++) mx = fmaxf(mx, red[i]);
        g_colmax[bh] = mx;
    }
    __syncthreads();
    if (tid < 64) {                          // col sums (reference "row")
        float s = 0.f;
        for (int m = 0; m < 64; m++) s += EB[m][tid];
        red[tid] = s;
    }
    __syncthreads();
    if (tid == 0) {
        float mx = red[0];
        for (int i = 1; i < 64; i++) mx = fmaxf(mx, red[i]);
        g_rowmax[bh] = mx;
    }
}

// ============== K5b: Moore-Penrose pinv + mid = pi @ (eC@v_aug) ==============
__global__ __launch_bounds__(1024) void pinv_kernel() {
    const int bh = blockIdx.x;
    const int h = bh & 7;
    __shared__ float Z[64][64];
    __shared__ float XZ[64][64];
    const int tid = threadIdx.x;
    const int i  = tid >> 4;
    const int j0 = (tid & 15) * 4;
    const float* Xg = g_eB + bh*LM*LM;
    float* Tg = g_T + bh*LM*LM;
    float* Ug = g_U + bh*LM*LM;

    // denom: max over batch per head
    const float colM = fmaxf(g_colmax[h], g_colmax[8 + h]);
    const float rowM = fmaxf(g_rowmax[h], g_rowmax[8 + h]);
    const float rden = 1.0f / (colM * rowM);

    // z = x^T / denom
    #pragma unroll
    for (int jj = 0; jj < 4; jj++)
        Z[i][j0+jj] = Xg[(j0+jj)*64 + i] * rden;
    __syncthreads();

    for (int it = 0; it < 6; it++) {
        {
            float a0=0,a1=0,a2=0,a3=0;
            for (int k = 0; k < 64; k++) {
                float a = Xg[i*64 + k];
                float4 bz = *(const float4*)&Z[k][j0];
                a0 += a*bz.x; a1 += a*bz.y; a2 += a*bz.z; a3 += a*bz.w;
            }
            XZ[i][j0+0]=a0; XZ[i][j0+1]=a1; XZ[i][j0+2]=a2; XZ[i][j0+3]=a3;
        }
        __syncthreads();
        {
            float a0=0,a1=0,a2=0,a3=0;
            for (int k = 0; k < 64; k++) {
                float a = XZ[i][k];
                float4 bz = *(const float4*)&XZ[k][j0];
                a0 += a*bz.x; a1 += a*bz.y; a2 += a*bz.z; a3 += a*bz.w;
            }
            float4 xz4 = *(const float4*)&XZ[i][j0];
            float4 o = make_float4(7.f*xz4.x - a0, 7.f*xz4.y - a1,
                                   7.f*xz4.z - a2, 7.f*xz4.w - a3);
            *(float4*)&Tg[i*64 + j0] = o;
        }
        __syncthreads();
        {
            float a0=0,a1=0,a2=0,a3=0;
            for (int k = 0; k < 64; k++) {
                float a = XZ[i][k];
                float4 bz = *(const float4*)&Tg[k*64 + j0];
                a0 += a*bz.x; a1 += a*bz.y; a2 += a*bz.z; a3 += a*bz.w;
            }
            float4 xz4 = *(const float4*)&XZ[i][j0];
            float4 o = make_float4(15.f*xz4.x - a0, 15.f*xz4.y - a1,
                                   15.f*xz4.z - a2, 15.f*xz4.w - a3);
            *(float4*)&Ug[i*64 + j0] = o;
        }
        __syncthreads();
        {
            float a0=0,a1=0,a2=0,a3=0;
            for (int k = 0; k < 64; k++) {
                float a = Z[i][k];
                float4 bz = *(const float4*)&Ug[k*64 + j0];
                a0 += a*bz.x; a1 += a*bz.y; a2 += a*bz.z; a3 += a*bz.w;
            }
            float4 z4 = *(const float4*)&Z[i][j0];
            float4 o = make_float4(0.25f*(13.f*z4.x - a0), 0.25f*(13.f*z4.y - a1),
                                   0.25f*(13.f*z4.z - a2), 0.25f*(13.f*z4.w - a3));
            *(float4*)&Tg[i*64 + j0] = o;
        }
        __syncthreads();
        *(float4*)&Z[i][j0] = *(const float4*)&Tg[i*64 + j0];
        __syncthreads();
    }

    {
        float4 s = make_float4(0,0,0,0);
        for (int c = 0; c < NCHUNK; c++) {
            float4 p = *(const float4*)&g_mid0p[(c*NBH + bh)*LM*HD + i*64 + j0];
            s.x += p.x; s.y += p.y; s.z += p.z; s.w += p.w;
        }
        *(float4*)&XZ[i][j0] = s;
    }
    __syncthreads();
    {
        float a0=0,a1=0,a2=0,a3=0;
        for (int k = 0; k < 64; k++) {
            float a = Z[i][k];
            float4 bz = *(const float4*)&XZ[k][j0];
            a0 += a*bz.x; a1 += a*bz.y; a2 += a*bz.z; a3 += a*bz.w;
        }
        float* mp = g_mid + bh*LM*(HD+1) + i*(HD+1) + j0;
        mp[0]=a0; mp[1]=a1; mp[2]=a2; mp[3]=a3;
    }
    if (tid < 64) {
        float s = 0.f;
        for (int k = 0; k < 64; k++) s += Z[tid][k] * g_esum[bh*LM + k];
        g_mid[bh*LM*(HD+1) + tid*(HD+1) + 64] = s;
    }
}

// ============== K6: out_p = softmax-ish(q_p@k_m^T) @ mid, divide ==============
__global__ __launch_bounds__(256) void nystrom_out_kernel() {
    const int bh = blockIdx.x;
    const int b = bh >> 3, h = bh & 7;
    const int qb = blockIdx.y;               // 0..31
    const float* qh = g_q + (b*NH + h)*SEQ*HD;
    __shared__ float A1[64][64];             // Qt[d][r] then P[r][k]
    __shared__ float A2[64][64];             // Kmt[d][k] then Ms[k][j]
    __shared__ float rm[64], den[64], mcol[64];
    const int tid = threadIdx.x;
    for (int i = tid; i < 64*16; i += 256) {
        int r = i >> 4; int s = (i & 15) * 4;
        float4 a = *(const float4*)&qh[(qb*64 + r)*HD + s];
        A1[s+0][r]=a.x; A1[s+1][r]=a.y; A1[s+2][r]=a.z; A1[s+3][r]=a.w;
        const float* kh = g_k + (b*NH + h)*SEQ*HD;
        float4 bb = *(const float4*)&kh[(r*LSTRIDE)*HD + s];
        A2[s+0][r]=bb.x; A2[s+1][r]=bb.y; A2[s+2][r]=bb.z; A2[s+3][r]=bb.w;
    }
    __syncthreads();
    const int tx = tid & 15, ty = tid >> 4;
    const int r0 = ty*4, k0 = tx*4;
    float acc[4][4] = {};
    #pragma unroll 8
    for (int d = 0; d < 64; d++) {
        float4 a = *(const float4*)&A1[d][r0];
        float4 bb = *(const float4*)&A2[d][k0];
        float Ar[4] = {a.x,a.y,a.z,a.w};
        float Br[4] = {bb.x,bb.y,bb.z,bb.w};
        #pragma unroll
        for (int ii = 0; ii < 4; ii++)
            #pragma unroll
            for (int jj = 0; jj < 4; jj++)
                acc[ii][jj] += Ar[ii]*Br[jj];
    }
    __syncthreads();
    #pragma unroll
    for (int ii = 0; ii < 4; ii++)
        #pragma unroll
        for (int jj = 0; jj < 4; jj++)
            A1[r0+ii][k0+jj] = acc[ii][jj];
    const float* mp = g_mid + bh*LM*(HD+1);
    for (int i = tid; i < 4096; i += 256) {
        int k = i >> 6, j = i & 63;
        A2[k][j] = mp[k*(HD+1) + j];
    }
    if (tid < 64) mcol[tid] = mp[tid*(HD+1) + 64];
    __syncthreads();
    if (tid < 64) {
        float mx = -1e30f;
        for (int k = 0; k < 64; k++) mx = fmaxf(mx, A1[tid][k]);
        rm[tid] = mx;
    }
    __syncthreads();
    for (int i = tid; i < 4096; i += 256) {
        int r = i >> 6, k = i & 63;
        A1[r][k] = __expf(A1[r][k] - rm[r]);
    }
    __syncthreads();
    if (tid < 64) {
        float s = 0.f;
        for (int k = 0; k < 64; k++) s += A1[tid][k] * mcol[k];
        den[tid] = s;
    }
    __syncthreads();
    float o[4][4] = {};
    #pragma unroll 8
    for (int k = 0; k < 64; k++) {
        float4 bb = *(const float4*)&A2[k][k0];
        float Br[4] = {bb.x,bb.y,bb.z,bb.w};
        #pragma unroll
        for (int ii = 0; ii < 4; ii++) {
            float a = A1[r0+ii][k];
            #pragma unroll
            for (int jj = 0; jj < 4; jj++)
                o[ii][jj] += a * Br[jj];
        }
    }
    #pragma unroll
    for (int ii = 0; ii < 4; ii++) {
        float inv = 1.0f / fmaxf(den[r0+ii], 1e-8f);
        int n = qb*64 + r0 + ii;
        float4 v = make_float4(o[ii][0]*inv, o[ii][1]*inv, o[ii][2]*inv, o[ii][3]*inv);
        *(float4*)&g_ctx[(b*SEQ + n)*EMB + h*HD + k0] = v;
    }
}

// =================================================================================
extern "C" void kernel_launch(void* const* d_in, const int* in_sizes, int n_in,
                              void* d_out, int out_size) {
    (void)in_sizes; (void)n_in; (void)out_size;
    const float* x      = (const float*)d_in[0];
    const float* qkv_w  = (const float*)d_in[1];
    const float* qkv_b  = (const float*)d_in[2];
    const float* proj_w = (const float*)d_in[3];
    const float* proj_b = (const float*)d_in[4];
    float* out = (float*)d_out;

    cudaFuncSetAttribute(flash_tf32, cudaFuncAttributeMaxDynamicSharedMemorySize, FLASH_SMEM);

    qkv_gemm_tf32<<<dim3(24, 32), 256>>>(x, qkv_w, qkv_b);
    sc_tf32<<<dim3(NBH, SEQ/64), 256>>>();
    rowstats_kernel<<<NBH*LM, 256>>>();
    ecv_tf32<<<dim3(NBH, NCHUNK), 256>>>();
    sb_kernel<<<NBH, 256>>>();
    pinv_kernel<<<NBH, 1024>>>();
    nystrom_out_kernel<<<dim3(NBH, SEQ/64), 256>>>();
    flash_tf32<<<dim3(NBH, SEQ/128), 256, FLASH_SMEM>>>();
    proj_gemm_tf32<<<dim3(8, 32), 256>>>(proj_w, proj_b, out);
}

// round 13
// speedup vs baseline: 1.0459x; 1.0001x over previous
#include <cuda_runtime.h>
#include <math.h>

#define BATCH 2
#define SEQ   2048
#define EMB   1024
#define NH    16
#define HD    64
#define PHH   8      // pnp heads
#define LM    64     // landmarks
#define NBH   16     // BATCH * PHH
#define QSCALE 0.125f
#define LSTRIDE 32   // SEQ / LM
#define NCHUNK 16    // ecv split-K chunks

// ---------------- scratch (device globals; no runtime allocation) ----------------
__device__ float g_q[BATCH*NH*SEQ*HD];
__device__ float g_k[BATCH*NH*SEQ*HD];
__device__ float g_v[BATCH*NH*SEQ*HD];
__device__ float g_SC[NBH*LM*SEQ];          // q_m @ k^T per pnp head
__device__ float g_scmax[NBH*LM];
__device__ float g_esum[NBH*LM];            // rowsum of eC
__device__ float g_mid0p[NCHUNK*NBH*LM*HD]; // split-K partials of eC @ v_p
__device__ float g_eB[NBH*LM*LM];
__device__ float g_T[NBH*LM*LM];            // pinv temp
__device__ float g_U[NBH*LM*LM];            // pinv temp
__device__ float g_colmax[NBH];
__device__ float g_rowmax[NBH];
__device__ float g_mid[NBH*LM*(HD+1)];      // pi @ (eC @ v_aug), 65 cols
__device__ float g_ctx[BATCH*SEQ*EMB];

// ---------------- tf32 mma helpers ----------------
__device__ __forceinline__ unsigned f2tf32(float x) {
    unsigned r;
    asm("cvt.rna.tf32.f32 %0, %1;" : "=r"(r) : "f"(x));
    return r;
}
__device__ __forceinline__ void mma8(float* c, const unsigned* a, const unsigned* b) {
    asm volatile(
        "mma.sync.aligned.m16n8k8.row.col.f32.tf32.tf32.f32 "
        "{%0,%1,%2,%3},{%4,%5,%6,%7},{%8,%9},{%0,%1,%2,%3};\n"
        : "+f"(c[0]), "+f"(c[1]), "+f"(c[2]), "+f"(c[3])
        : "r"(a[0]), "r"(a[1]), "r"(a[2]), "r"(a[3]), "r"(b[0]), "r"(b[1]));
}
__device__ __forceinline__ uint4 cvt4(float4 v) {
    uint4 u;
    u.x = f2tf32(v.x); u.y = f2tf32(v.y); u.z = f2tf32(v.z); u.w = f2tf32(v.w);
    return u;
}

// ======================= K1: QKV GEMM (tf32, 128x128x32 tiles) =======================
__global__ __launch_bounds__(256) void qkv_gemm_tf32(const float* __restrict__ X,
                                                     const float* __restrict__ W,
                                                     const float* __restrict__ bias) {
    __shared__ unsigned As[128][36];   // [m][k], k-tile 32, pad 36
    __shared__ unsigned Bs[128][36];   // [n][k]
    const int bi = blockIdx.y * 128;
    const int bj = blockIdx.x * 128;
    const int tid = threadIdx.x, warp = tid >> 5, lane = tid & 31;
    const int g = lane >> 2, tig = lane & 3;
    const int wm = (warp & 1) * 64, wn = (warp >> 1) * 32;
    float c[4][4][4] = {};
    const int lr = tid >> 1, lc = (tid & 1) * 16;
    const float* ax = X + (bi + lr) * EMB + lc;
    const float* bx = W + (bj + lr) * EMB + lc;
    float4 pa[4], pb[4];
    #pragma unroll
    for (int i = 0; i < 4; i++) {
        pa[i] = *(const float4*)(ax + i*4);
        pb[i] = *(const float4*)(bx + i*4);
    }
    for (int k0 = 0; k0 < EMB; k0 += 32) {
        #pragma unroll
        for (int i = 0; i < 4; i++) {
            *(uint4*)&As[lr][lc + i*4] = cvt4(pa[i]);
            *(uint4*)&Bs[lr][lc + i*4] = cvt4(pb[i]);
        }
        __syncthreads();
        if (k0 < EMB - 32) {
            #pragma unroll
            for (int i = 0; i < 4; i++) {
                pa[i] = *(const float4*)(ax + k0 + 32 + i*4);
                pb[i] = *(const float4*)(bx + k0 + 32 + i*4);
            }
        }
        #pragma unroll
        for (int ks = 0; ks < 4; ks++) {
            unsigned a[4][4], bb[4][2];
            #pragma unroll
            for (int mf = 0; mf < 4; mf++) {
                const unsigned* p = &As[wm + mf*16 + g][ks*8 + tig];
                a[mf][0] = p[0];
                a[mf][1] = p[8*36];
                a[mf][2] = p[4];
                a[mf][3] = p[8*36 + 4];
            }
            #pragma unroll
            for (int nf = 0; nf < 4; nf++) {
                const unsigned* p = &Bs[wn + nf*8 + g][ks*8 + tig];
                bb[nf][0] = p[0];
                bb[nf][1] = p[4];
            }
            #pragma unroll
            for (int mf = 0; mf < 4; mf++)
                #pragma unroll
                for (int nf = 0; nf < 4; nf++)
                    mma8(c[mf][nf], a[mf], bb[nf]);
        }
        __syncthreads();
    }
    // epilogue: scatter into q/k/v [B][H][N][D], scale q
    #pragma unroll
    for (int mf = 0; mf < 4; mf++) {
        #pragma unroll
        for (int nf = 0; nf < 4; nf++) {
            int gj = bj + wn + nf*8 + tig*2;
            int s  = gj >> 10;
            int hh = (gj >> 6) & 15;
            int dd = gj & 63;
            float b0 = bias[gj], b1 = bias[gj + 1];
            float* dst = (s == 0) ? g_q : (s == 1) ? g_k : g_v;
            float mul = (s == 0) ? QSCALE : 1.0f;
            int gi = bi + wm + mf*16 + g;
            int bb2 = gi >> 11, n = gi & 2047;
            float2 v0 = make_float2((c[mf][nf][0] + b0) * mul, (c[mf][nf][1] + b1) * mul);
            *(float2*)&dst[((bb2*NH + hh)*SEQ + n)*HD + dd] = v0;
            float2 v1 = make_float2((c[mf][nf][2] + b0) * mul, (c[mf][nf][3] + b1) * mul);
            *(float2*)&dst[((bb2*NH + hh)*SEQ + n + 8)*HD + dd] = v1;
        }
    }
}

// ======================= K8: output projection GEMM (tf32, k-tile 32) =======================
__global__ __launch_bounds__(256) void proj_gemm_tf32(const float* __restrict__ W,
                                                      const float* __restrict__ bias,
                                                      float* __restrict__ out) {
    __shared__ unsigned As[128][36];
    __shared__ unsigned Bs[128][36];
    const int bi = blockIdx.y * 128;
    const int bj = blockIdx.x * 128;
    const int tid = threadIdx.x, warp = tid >> 5, lane = tid & 31;
    const int g = lane >> 2, tig = lane & 3;
    const int wm = (warp & 1) * 64, wn = (warp >> 1) * 32;
    float c[4][4][4] = {};
    const int lr = tid >> 1, lc = (tid & 1) * 16;
    const float* ax = g_ctx + (bi + lr) * EMB + lc;
    const float* bx = W + (bj + lr) * EMB + lc;
    float4 pa[4], pb[4];
    #pragma unroll
    for (int i = 0; i < 4; i++) {
        pa[i] = *(const float4*)(ax + i*4);
        pb[i] = *(const float4*)(bx + i*4);
    }
    for (int k0 = 0; k0 < EMB; k0 += 32) {
        #pragma unroll
        for (int i = 0; i < 4; i++) {
            *(uint4*)&As[lr][lc + i*4] = cvt4(pa[i]);
            *(uint4*)&Bs[lr][lc + i*4] = cvt4(pb[i]);
        }
        __syncthreads();
        if (k0 < EMB - 32) {
            #pragma unroll
            for (int i = 0; i < 4; i++) {
                pa[i] = *(const float4*)(ax + k0 + 32 + i*4);
                pb[i] = *(const float4*)(bx + k0 + 32 + i*4);
            }
        }
        #pragma unroll
        for (int ks = 0; ks < 4; ks++) {
            unsigned a[4][4], bb[4][2];
            #pragma unroll
            for (int mf = 0; mf < 4; mf++) {
                const unsigned* p = &As[wm + mf*16 + g][ks*8 + tig];
                a[mf][0] = p[0];
                a[mf][1] = p[8*36];
                a[mf][2] = p[4];
                a[mf][3] = p[8*36 + 4];
            }
            #pragma unroll
            for (int nf = 0; nf < 4; nf++) {
                const unsigned* p = &Bs[wn + nf*8 + g][ks*8 + tig];
                bb[nf][0] = p[0];
                bb[nf][1] = p[4];
            }
            #pragma unroll
            for (int mf = 0; mf < 4; mf++)
                #pragma unroll
                for (int nf = 0; nf < 4; nf++)
                    mma8(c[mf][nf], a[mf], bb[nf]);
        }
        __syncthreads();
    }
    #pragma unroll
    for (int mf = 0; mf < 4; mf++) {
        #pragma unroll
        for (int nf = 0; nf < 4; nf++) {
            int gj = bj + wn + nf*8 + tig*2;
            float b0 = bias[gj], b1 = bias[gj + 1];
            int gi = bi + wm + mf*16 + g;
            float2 v0 = make_float2(c[mf][nf][0] + b0, c[mf][nf][1] + b1);
            *(float2*)&out[gi * EMB + gj] = v0;
            float2 v1 = make_float2(c[mf][nf][2] + b0, c[mf][nf][3] + b1);
            *(float2*)&out[(gi + 8) * EMB + gj] = v1;
        }
    }
}

// ======================= K7: flash attention (tf32 mma, single-buffer K/V reg prefetch) =======================
// Block: 128 query rows of one full-softmax head. 8 warps, each owns 16 rows.
// Dynamic smem: Qs[128][68] + Ks[64][68] + Vs[64][68] + Ps[128][68] = 104448 B (2 CTAs/SM)
#define FLASH_SMEM (68 * 384 * 4)
__global__ __launch_bounds__(256, 2) void flash_tf32() {
    extern __shared__ char smraw[];
    unsigned* Qs = (unsigned*)smraw;          // [128][68]
    unsigned* Ks = Qs + 128 * 68;             // [64][68]
    unsigned* Vs = Ks + 64 * 68;              // [64][68]
    unsigned* Ps = Vs + 64 * 68;              // [128][68] tf32 P
    const int bh = blockIdx.x, qb = blockIdx.y;
    const int b = bh >> 3, h = 8 + (bh & 7);
    const float* qh = g_q + (b*NH + h)*SEQ*HD;
    const float* kh = g_k + (b*NH + h)*SEQ*HD;
    const float* vh = g_v + (b*NH + h)*SEQ*HD;
    const int tid = threadIdx.x, warp = tid >> 5, lane = tid & 31;
    const int g = lane >> 2, tig = lane & 3;
    const int rowA = warp * 16 + g;           // this thread's base row (also rowA+8)

    // load Q tile (128 x 64) as tf32
    {
        int r = tid >> 1, c0 = (tid & 1) * 32;
        const float* src = qh + (qb*128 + r)*HD + c0;
        unsigned* dst = Qs + r*68 + c0;
        #pragma unroll
        for (int i = 0; i < 8; i++)
            *(uint4*)(dst + i*4) = cvt4(*(const float4*)(src + i*4));
    }
    // prefetch K/V tile 0 into registers (tf32-converted)
    const int kvr = tid >> 2, kvc = (tid & 3) * 16;
    uint4 qk[4], qv[4];
    #pragma unroll
    for (int i = 0; i < 4; i++) {
        qk[i] = cvt4(*(const float4*)(kh + kvr*HD + kvc + i*4));
        qv[i] = cvt4(*(const float4*)(vh + kvr*HD + kvc + i*4));
    }

    float o[8][4] = {};
    float mrow[2] = {-1e30f, -1e30f};
    float lrow[2] = {0.f, 0.f};

    for (int t = 0; t < SEQ/64; t++) {
        __syncthreads();   // reads of tile t-1 done (t>0); Q store pre-loop ordered too
        // store prefetched tile t into the single K/V buffer
        #pragma unroll
        for (int i = 0; i < 4; i++) {
            *(uint4*)(Ks + kvr*68 + kvc + i*4) = qk[i];
            *(uint4*)(Vs + kvr*68 + kvc + i*4) = qv[i];
        }
        __syncthreads();   // tile t visible
        // issue LDG for tile t+1; latency hides under both mma phases below
        if (t + 1 < SEQ/64) {
            const float* ks = kh + ((t+1)*64 + kvr)*HD + kvc;
            const float* vs = vh + ((t+1)*64 + kvr)*HD + kvc;
            #pragma unroll
            for (int i = 0; i < 4; i++) {
                qk[i] = cvt4(*(const float4*)(ks + i*4));
                qv[i] = cvt4(*(const float4*)(vs + i*4));
            }
        }

        // S = Q @ K^T for this warp's 16 rows x 64 key-cols
        float s[8][4] = {};
        #pragma unroll
        for (int k8 = 0; k8 < 8; k8++) {
            unsigned a[4];
            const unsigned* qp = Qs + rowA*68 + k8*8;
            a[0] = qp[tig]; a[1] = qp[8*68 + tig];
            a[2] = qp[tig + 4]; a[3] = qp[8*68 + tig + 4];
            #pragma unroll
            for (int nf = 0; nf < 8; nf++) {
                unsigned bfr[2];
                const unsigned* kp = Ks + (nf*8 + g)*68 + k8*8;
                bfr[0] = kp[tig]; bfr[1] = kp[tig + 4];
                mma8(s[nf], a, bfr);
            }
        }
        // online softmax (rows rowA and rowA+8)
        float mx0 = -1e30f, mx1 = -1e30f;
        #pragma unroll
        for (int nf = 0; nf < 8; nf++) {
            mx0 = fmaxf(mx0, fmaxf(s[nf][0], s[nf][1]));
            mx1 = fmaxf(mx1, fmaxf(s[nf][2], s[nf][3]));
        }
        mx0 = fmaxf(mx0, __shfl_xor_sync(0xffffffffu, mx0, 1));
        mx0 = fmaxf(mx0, __shfl_xor_sync(0xffffffffu, mx0, 2));
        mx1 = fmaxf(mx1, __shfl_xor_sync(0xffffffffu, mx1, 1));
        mx1 = fmaxf(mx1, __shfl_xor_sync(0xffffffffu, mx1, 2));
        float mn0 = fmaxf(mrow[0], mx0), mn1 = fmaxf(mrow[1], mx1);
        float sc0 = __expf(mrow[0] - mn0), sc1 = __expf(mrow[1] - mn1);
        float ls0 = 0.f, ls1 = 0.f;
        #pragma unroll
        for (int nf = 0; nf < 8; nf++) {
            float p0 = __expf(s[nf][0] - mn0);
            float p1 = __expf(s[nf][1] - mn0);
            float p2 = __expf(s[nf][2] - mn1);
            float p3 = __expf(s[nf][3] - mn1);
            ls0 += p0 + p1; ls1 += p2 + p3;
            uint2 u0; u0.x = f2tf32(p0); u0.y = f2tf32(p1);
            *(uint2*)(Ps + rowA*68 + nf*8 + tig*2) = u0;
            uint2 u1; u1.x = f2tf32(p2); u1.y = f2tf32(p3);
            *(uint2*)(Ps + (rowA + 8)*68 + nf*8 + tig*2) = u1;
        }
        ls0 += __shfl_xor_sync(0xffffffffu, ls0, 1);
        ls0 += __shfl_xor_sync(0xffffffffu, ls0, 2);
        ls1 += __shfl_xor_sync(0xffffffffu, ls1, 1);
        ls1 += __shfl_xor_sync(0xffffffffu, ls1, 2);
        lrow[0] = lrow[0]*sc0 + ls0;
        lrow[1] = lrow[1]*sc1 + ls1;
        mrow[0] = mn0; mrow[1] = mn1;
        #pragma unroll
        for (int nf = 0; nf < 8; nf++) {
            o[nf][0] *= sc0; o[nf][1] *= sc0;
            o[nf][2] *= sc1; o[nf][3] *= sc1;
        }
        __syncwarp();   // P written (own warp's rows) before fragment reload

        // out += P @ V
        #pragma unroll
        for (int k8 = 0; k8 < 8; k8++) {
            unsigned a[4];
            const unsigned* pp = Ps + rowA*68 + k8*8;
            a[0] = pp[tig];
            a[1] = pp[8*68 + tig];
            a[2] = pp[tig + 4];
            a[3] = pp[8*68 + tig + 4];
            #pragma unroll
            for (int nf = 0; nf < 8; nf++) {
                unsigned bfr[2];
                const unsigned* vp = Vs + (k8*8 + tig)*68 + nf*8 + g;
                bfr[0] = vp[0]; bfr[1] = vp[4*68];
                mma8(o[nf], a, bfr);
            }
        }
    }
    // epilogue
    float inv0 = 1.0f / lrow[0], inv1 = 1.0f / lrow[1];
    int n0 = qb*128 + rowA;
    #pragma unroll
    for (int nf = 0; nf < 8; nf++) {
        int d = nf*8 + tig*2;
        float2 v0 = make_float2(o[nf][0]*inv0, o[nf][1]*inv0);
        *(float2*)&g_ctx[(b*SEQ + n0)*EMB + h*HD + d] = v0;
        float2 v1 = make_float2(o[nf][2]*inv1, o[nf][3]*inv1);
        *(float2*)&g_ctx[(b*SEQ + n0 + 8)*EMB + h*HD + d] = v1;
    }
}

// ======================= K2: SC = q_m @ k^T (tf32 mma, 64x64 tile) =======================
__global__ __launch_bounds__(256) void sc_tf32() {
    const int bh = blockIdx.x;               // b*8+h
    const int b = bh >> 3, h = bh & 7;
    const int n0 = blockIdx.y * 64;
    const float* qh = g_q + (b*NH + h)*SEQ*HD;
    const float* kh = g_k + (b*NH + h)*SEQ*HD;
    __shared__ unsigned Qm[64][68];          // [m][d] landmark rows (d=64, pad 68)
    __shared__ unsigned Kn[64][68];          // [n][d]
    const int tid = threadIdx.x, warp = tid >> 5, lane = tid & 31;
    const int g = lane >> 2, tig = lane & 3;
    {
        int r = tid >> 2, c = (tid & 3) * 16;
        const float* qs = qh + (r*LSTRIDE)*HD + c;
        const float* ks = kh + (n0 + r)*HD + c;
        #pragma unroll
        for (int i = 0; i < 4; i++) {
            *(uint4*)&Qm[r][c + i*4] = cvt4(*(const float4*)(qs + i*4));
            *(uint4*)&Kn[r][c + i*4] = cvt4(*(const float4*)(ks + i*4));
        }
    }
    __syncthreads();
    const int wm = (warp & 3) * 16, wn = (warp >> 2) * 32;
    float c4[4][4] = {};
    #pragma unroll
    for (int k8 = 0; k8 < 8; k8++) {
        unsigned a[4];
        a[0] = Qm[wm + g][k8*8 + tig];
        a[1] = Qm[wm + g + 8][k8*8 + tig];
        a[2] = Qm[wm + g][k8*8 + tig + 4];
        a[3] = Qm[wm + g + 8][k8*8 + tig + 4];
        #pragma unroll
        for (int nf = 0; nf < 4; nf++) {
            unsigned bb[2];
            bb[0] = Kn[wn + nf*8 + g][k8*8 + tig];
            bb[1] = Kn[wn + nf*8 + g][k8*8 + tig + 4];
            mma8(c4[nf], a, bb);
        }
    }
    float* scp = g_SC + bh*LM*SEQ;
    #pragma unroll
    for (int nf = 0; nf < 4; nf++) {
        int n = n0 + wn + nf*8 + tig*2;
        *(float2*)&scp[(wm + g)*SEQ + n]     = make_float2(c4[nf][0], c4[nf][1]);
        *(float2*)&scp[(wm + g + 8)*SEQ + n] = make_float2(c4[nf][2], c4[nf][3]);
    }
}

// ============== K3: per-row max + exp-sum of SC ==============
__global__ __launch_bounds__(256) void rowstats_kernel() {
    const int row = blockIdx.x;              // bh*64 + m
    const float* sp = g_SC + row * SEQ;
    __shared__ float red[256];
    const int tid = threadIdx.x;
    float mx = -1e30f;
    for (int n = tid; n < SEQ; n += 256) mx = fmaxf(mx, sp[n]);
    red[tid] = mx; __syncthreads();
    for (int o = 128; o > 0; o >>= 1) {
        if (tid < o) red[tid] = fmaxf(red[tid], red[tid+o]);
        __syncthreads();
    }
    const float m = red[0];
    __syncthreads();
    float s = 0.f;
    for (int n = tid; n < SEQ; n += 256) s += __expf(sp[n] - m);
    red[tid] = s; __syncthreads();
    for (int o = 128; o > 0; o >>= 1) {
        if (tid < o) red[tid] += red[tid+o];
        __syncthreads();
    }
    if (tid == 0) { g_scmax[row] = m; g_esum[row] = red[0]; }
}

// ============== K4: split-K partials of eC @ v_p (tf32 mma) ==============
__global__ __launch_bounds__(256) void ecv_tf32() {
    const int bh = blockIdx.x;
    const int b = bh >> 3, h = bh & 7;
    const int chunk = blockIdx.y;            // 0..15 -> n range of 128
    const float* vh = g_v + (b*NH + h)*SEQ*HD;
    const float* scp = g_SC + bh*LM*SEQ;
    __shared__ unsigned Et[64][68];          // [n_local][m]  exp values, tf32
    __shared__ unsigned Vs[64][68];          // [n_local][d]  tf32
    __shared__ float mx_s[64];
    const int tid = threadIdx.x, warp = tid >> 5, lane = tid & 31;
    const int g = lane >> 2, tig = lane & 3;
    const int wm = (warp & 3) * 16, wn = (warp >> 2) * 32;
    if (tid < 64) mx_s[tid] = g_scmax[bh*LM + tid];
    float acc[4][4] = {};
    for (int sub = 0; sub < 2; sub++) {
        const int nbase = chunk*128 + sub*64;
        __syncthreads();
        for (int i = tid; i < 64*16; i += 256) {
            int m = i >> 4; int s = (i & 15) * 4;
            float mxv = mx_s[m];
            float4 a = *(const float4*)&scp[m*SEQ + nbase + s];
            Et[s+0][m] = f2tf32(__expf(a.x - mxv));
            Et[s+1][m] = f2tf32(__expf(a.y - mxv));
            Et[s+2][m] = f2tf32(__expf(a.z - mxv));
            Et[s+3][m] = f2tf32(__expf(a.w - mxv));
        }
        {
            int r = tid >> 2, c = (tid & 3) * 16;
            const float* vs = vh + (nbase + r)*HD + c;
            #pragma unroll
            for (int i = 0; i < 4; i++)
                *(uint4*)&Vs[r][c + i*4] = cvt4(*(const float4*)(vs + i*4));
        }
        __syncthreads();
        #pragma unroll
        for (int k8 = 0; k8 < 8; k8++) {
            unsigned a[4];
            a[0] = Et[k8*8 + tig][wm + g];
            a[1] = Et[k8*8 + tig][wm + g + 8];
            a[2] = Et[k8*8 + tig + 4][wm + g];
            a[3] = Et[k8*8 + tig + 4][wm + g + 8];
            #pragma unroll
            for (int nf = 0; nf < 4; nf++) {
                unsigned bb[2];
                int d = wn + nf*8 + g;
                bb[0] = Vs[k8*8 + tig][d];
                bb[1] = Vs[k8*8 + tig + 4][d];
                mma8(acc[nf], a, bb);
            }
        }
    }
    float* dst = g_mid0p + (chunk*NBH + bh)*LM*HD;
    #pragma unroll
    for (int nf = 0; nf < 4; nf++) {
        int d = wn + nf*8 + tig*2;
        *(float2*)&dst[(wm + g)*HD + d]     = make_float2(acc[nf][0], acc[nf][1]);
        *(float2*)&dst[(wm + g + 8)*HD + d] = make_float2(acc[nf][2], acc[nf][3]);
    }
}

// ============== K5a: SB, eB, row/col-sum maxima ==============
__global__ __launch_bounds__(256) void sb_kernel() {
    const int bh = blockIdx.x;
    const int b = bh >> 3, h = bh & 7;
    const float* qh = g_q + (b*NH + h)*SEQ*HD;
    const float* kh = g_k + (b*NH + h)*SEQ*HD;
    __shared__ float Qt[64][64];             // [d][m], later reused as EB[m][k]
    __shared__ float Kt[64][64];             // [d][k]
    __shared__ float red[64];
    const int tid = threadIdx.x;
    for (int i = tid; i < 64*16; i += 256) {
        int r = i >> 4; int s = (i & 15) * 4;
        float4 a = *(const float4*)&qh[(r*LSTRIDE)*HD + s];
        Qt[s+0][r]=a.x; Qt[s+1][r]=a.y; Qt[s+2][r]=a.z; Qt[s+3][r]=a.w;
        float4 bb = *(const float4*)&kh[(r*LSTRIDE)*HD + s];
        Kt[s+0][r]=bb.x; Kt[s+1][r]=bb.y; Kt[s+2][r]=bb.z; Kt[s+3][r]=bb.w;
    }
    __syncthreads();
    const int tx = tid & 15, ty = tid >> 4;
    const int m0 = ty*4, k0 = tx*4;
    float acc[4][4] = {};
    #pragma unroll 8
    for (int d = 0; d < 64; d++) {
        float4 a = *(const float4*)&Qt[d][m0];
        float4 bb = *(const float4*)&Kt[d][k0];
        float Ar[4] = {a.x,a.y,a.z,a.w};
        float Br[4] = {bb.x,bb.y,bb.z,bb.w};
        #pragma unroll
        for (int ii = 0; ii < 4; ii++)
            #pragma unroll
            for (int jj = 0; jj < 4; jj++)
                acc[ii][jj] += Ar[ii]*Br[jj];
    }
    __syncthreads();                         // Qt now dead -> reuse as EB
    float (*EB)[64] = Qt;
    #pragma unroll
    for (int ii = 0; ii < 4; ii++) {
        float mx = g_scmax[bh*LM + m0 + ii];
        #pragma unroll
        for (int jj = 0; jj < 4; jj++) {
            float e = __expf(fmaxf(acc[ii][jj] - mx, -88.0f));
            EB[m0+ii][k0+jj] = e;
            g_eB[bh*LM*LM + (m0+ii)*LM + k0 + jj] = e;
        }
    }
    __syncthreads();
    if (tid < 64) {                          // row sums (reference "col")
        float s = 0.f;
        for (int k = 0; k < 64; k++) s += EB[tid][k];
        red[tid] = s;
    }
    __syncthreads();
    if (tid == 0) {
        float mx = red[0];
        for (int i = 1; i < 64; i++) mx = fmaxf(mx, red[i]);
        g_colmax[bh] = mx;
    }
    __syncthreads();
    if (tid < 64) {                          // col sums (reference "row")
        float s = 0.f;
        for (int m = 0; m < 64; m++) s += EB[m][tid];
        red[tid] = s;
    }
    __syncthreads();
    if (tid == 0) {
        float mx = red[0];
        for (int i = 1; i < 64; i++) mx = fmaxf(mx, red[i]);
        g_rowmax[bh] = mx;
    }
}

// ============== K5b: Moore-Penrose pinv + mid = pi @ (eC@v_aug) ==============
__global__ __launch_bounds__(1024) void pinv_kernel() {
    const int bh = blockIdx.x;
    const int h = bh & 7;
    __shared__ float Z[64][64];
    __shared__ float XZ[64][64];
    const int tid = threadIdx.x;
    const int i  = tid >> 4;
    const int j0 = (tid & 15) * 4;
    const float* Xg = g_eB + bh*LM*LM;
    float* Tg = g_T + bh*LM*LM;
    float* Ug = g_U + bh*LM*LM;

    // denom: max over batch per head
    const float colM = fmaxf(g_colmax[h], g_colmax[8 + h]);
    const float rowM = fmaxf(g_rowmax[h], g_rowmax[8 + h]);
    const float rden = 1.0f / (colM * rowM);

    // z = x^T / denom
    #pragma unroll
    for (int jj = 0; jj < 4; jj++)
        Z[i][j0+jj] = Xg[(j0+jj)*64 + i] * rden;
    __syncthreads();

    for (int it = 0; it < 6; it++) {
        {
            float a0=0,a1=0,a2=0,a3=0;
            for (int k = 0; k < 64; k++) {
                float a = Xg[i*64 + k];
                float4 bz = *(const float4*)&Z[k][j0];
                a0 += a*bz.x; a1 += a*bz.y; a2 += a*bz.z; a3 += a*bz.w;
            }
            XZ[i][j0+0]=a0; XZ[i][j0+1]=a1; XZ[i][j0+2]=a2; XZ[i][j0+3]=a3;
        }
        __syncthreads();
        {
            float a0=0,a1=0,a2=0,a3=0;
            for (int k = 0; k < 64; k++) {
                float a = XZ[i][k];
                float4 bz = *(const float4*)&XZ[k][j0];
                a0 += a*bz.x; a1 += a*bz.y; a2 += a*bz.z; a3 += a*bz.w;
            }
            float4 xz4 = *(const float4*)&XZ[i][j0];
            float4 o = make_float4(7.f*xz4.x - a0, 7.f*xz4.y - a1,
                                   7.f*xz4.z - a2, 7.f*xz4.w - a3);
            *(float4*)&Tg[i*64 + j0] = o;
        }
        __syncthreads();
        {
            float a0=0,a1=0,a2=0,a3=0;
            for (int k = 0; k < 64; k++) {
                float a = XZ[i][k];
                float4 bz = *(const float4*)&Tg[k*64 + j0];
                a0 += a*bz.x; a1 += a*bz.y; a2 += a*bz.z; a3 += a*bz.w;
            }
            float4 xz4 = *(const float4*)&XZ[i][j0];
            float4 o = make_float4(15.f*xz4.x - a0, 15.f*xz4.y - a1,
                                   15.f*xz4.z - a2, 15.f*xz4.w - a3);
            *(float4*)&Ug[i*64 + j0] = o;
        }
        __syncthreads();
        {
            float a0=0,a1=0,a2=0,a3=0;
            for (int k = 0; k < 64; k++) {
                float a = Z[i][k];
                float4 bz = *(const float4*)&Ug[k*64 + j0];
                a0 += a*bz.x; a1 += a*bz.y; a2 += a*bz.z; a3 += a*bz.w;
            }
            float4 z4 = *(const float4*)&Z[i][j0];
            float4 o = make_float4(0.25f*(13.f*z4.x - a0), 0.25f*(13.f*z4.y - a1),
                                   0.25f*(13.f*z4.z - a2), 0.25f*(13.f*z4.w - a3));
            *(float4*)&Tg[i*64 + j0] = o;
        }
        __syncthreads();
        *(float4*)&Z[i][j0] = *(const float4*)&Tg[i*64 + j0];
        __syncthreads();
    }

    {
        float4 s = make_float4(0,0,0,0);
        for (int c = 0; c < NCHUNK; c++) {
            float4 p = *(const float4*)&g_mid0p[(c*NBH + bh)*LM*HD + i*64 + j0];
            s.x += p.x; s.y += p.y; s.z += p.z; s.w += p.w;
        }
        *(float4*)&XZ[i][j0] = s;
    }
    __syncthreads();
    {
        float a0=0,a1=0,a2=0,a3=0;
        for (int k = 0; k < 64; k++) {
            float a = Z[i][k];
            float4 bz = *(const float4*)&XZ[k][j0];
            a0 += a*bz.x; a1 += a*bz.y; a2 += a*bz.z; a3 += a*bz.w;
        }
        float* mp = g_mid + bh*LM*(HD+1) + i*(HD+1) + j0;
        mp[0]=a0; mp[1]=a1; mp[2]=a2; mp[3]=a3;
    }
    if (tid < 64) {
        float s = 0.f;
        for (int k = 0; k < 64; k++) s += Z[tid][k] * g_esum[bh*LM + k];
        g_mid[bh*LM*(HD+1) + tid*(HD+1) + 64] = s;
    }
}

// ============== K6: out_p = softmax-ish(q_p@k_m^T) @ mid, divide ==============
__global__ __launch_bounds__(256) void nystrom_out_kernel() {
    const int bh = blockIdx.x;
    const int b = bh >> 3, h = bh & 7;
    const int qb = blockIdx.y;               // 0..31
    const float* qh = g_q + (b*NH + h)*SEQ*HD;
    __shared__ float A1[64][64];             // Qt[d][r] then P[r][k]
    __shared__ float A2[64][64];             // Kmt[d][k] then Ms[k][j]
    __shared__ float rm[64], den[64], mcol[64];
    const int tid = threadIdx.x;
    for (int i = tid; i < 64*16; i += 256) {
        int r = i >> 4; int s = (i & 15) * 4;
        float4 a = *(const float4*)&qh[(qb*64 + r)*HD + s];
        A1[s+0][r]=a.x; A1[s+1][r]=a.y; A1[s+2][r]=a.z; A1[s+3][r]=a.w;
        const float* kh = g_k + (b*NH + h)*SEQ*HD;
        float4 bb = *(const float4*)&kh[(r*LSTRIDE)*HD + s];
        A2[s+0][r]=bb.x; A2[s+1][r]=bb.y; A2[s+2][r]=bb.z; A2[s+3][r]=bb.w;
    }
    __syncthreads();
    const int tx = tid & 15, ty = tid >> 4;
    const int r0 = ty*4, k0 = tx*4;
    float acc[4][4] = {};
    #pragma unroll 8
    for (int d = 0; d < 64; d++) {
        float4 a = *(const float4*)&A1[d][r0];
        float4 bb = *(const float4*)&A2[d][k0];
        float Ar[4] = {a.x,a.y,a.z,a.w};
        float Br[4] = {bb.x,bb.y,bb.z,bb.w};
        #pragma unroll
        for (int ii = 0; ii < 4; ii++)
            #pragma unroll
            for (int jj = 0; jj < 4; jj++)
                acc[ii][jj] += Ar[ii]*Br[jj];
    }
    __syncthreads();
    #pragma unroll
    for (int ii = 0; ii < 4; ii++)
        #pragma unroll
        for (int jj = 0; jj < 4; jj++)
            A1[r0+ii][k0+jj] = acc[ii][jj];
    const float* mp = g_mid + bh*LM*(HD+1);
    for (int i = tid; i < 4096; i += 256) {
        int k = i >> 6, j = i & 63;
        A2[k][j] = mp[k*(HD+1) + j];
    }
    if (tid < 64) mcol[tid] = mp[tid*(HD+1) + 64];
    __syncthreads();
    if (tid < 64) {
        float mx = -1e30f;
        for (int k = 0; k < 64; k++) mx = fmaxf(mx, A1[tid][k]);
        rm[tid] = mx;
    }
    __syncthreads();
    for (int i = tid; i < 4096; i += 256) {
        int r = i >> 6, k = i & 63;
        A1[r][k] = __expf(A1[r][k] - rm[r]);
    }
    __syncthreads();
    if (tid < 64) {
        float s = 0.f;
        for (int k = 0; k < 64; k++) s += A1[tid][k] * mcol[k];
        den[tid] = s;
    }
    __syncthreads();
    float o[4][4] = {};
    #pragma unroll 8
    for (int k = 0; k < 64; k++) {
        float4 bb = *(const float4*)&A2[k][k0];
        float Br[4] = {bb.x,bb.y,bb.z,bb.w};
        #pragma unroll
        for (int ii = 0; ii < 4; ii++) {
            float a = A1[r0+ii][k];
            #pragma unroll
            for (int jj = 0; jj < 4; jj++)
                o[ii][jj] += a * Br[jj];
        }
    }
    #pragma unroll
    for (int ii = 0; ii < 4; ii++) {
        float inv = 1.0f / fmaxf(den[r0+ii], 1e-8f);
        int n = qb*64 + r0 + ii;
        float4 v = make_float4(o[ii][0]*inv, o[ii][1]*inv, o[ii][2]*inv, o[ii][3]*inv);
        *(float4*)&g_ctx[(b*SEQ + n)*EMB + h*HD + k0] = v;
    }
}

// =================================================================================
extern "C" void kernel_launch(void* const* d_in, const int* in_sizes, int n_in,
                              void* d_out, int out_size) {
    (void)in_sizes; (void)n_in; (void)out_size;
    const float* x      = (const float*)d_in[0];
    const float* qkv_w  = (const float*)d_in[1];
    const float* qkv_b  = (const float*)d_in[2];
    const float* proj_w = (const float*)d_in[3];
    const float* proj_b = (const float*)d_in[4];
    float* out = (float*)d_out;

    cudaFuncSetAttribute(flash_tf32, cudaFuncAttributeMaxDynamicSharedMemorySize, FLASH_SMEM);

    qkv_gemm_tf32<<<dim3(24, 32), 256>>>(x, qkv_w, qkv_b);
    sc_tf32<<<dim3(NBH, SEQ/64), 256>>>();
    rowstats_kernel<<<NBH*LM, 256>>>();
    ecv_tf32<<<dim3(NBH, NCHUNK), 256>>>();
    sb_kernel<<<NBH, 256>>>();
    pinv_kernel<<<NBH, 1024>>>();
    nystrom_out_kernel<<<dim3(NBH, SEQ/64), 256>>>();
    flash_tf32<<<dim3(NBH, SEQ/128), 256, FLASH_SMEM>>>();
    proj_gemm_tf32<<<dim3(8, 32), 256>>>(proj_w, proj_b, out);
}

// round 14
// speedup vs baseline: 1.0488x; 1.0028x over previous
#include <cuda_runtime.h>
#include <math.h>

#define BATCH 2
#define SEQ   2048
#define EMB   1024
#define NH    16
#define HD    64
#define PHH   8      // pnp heads
#define LM    64     // landmarks
#define NBH   16     // BATCH * PHH
#define QSCALE 0.125f
#define LSTRIDE 32   // SEQ / LM
#define NCHUNK 16    // ecv split-K chunks

// ---------------- scratch (device globals; no runtime allocation) ----------------
__device__ float g_q[BATCH*NH*SEQ*HD];
__device__ float g_k[BATCH*NH*SEQ*HD];
__device__ float g_v[BATCH*NH*SEQ*HD];
__device__ float g_SC[NBH*LM*SEQ];          // q_m @ k^T per pnp head
__device__ float g_scmax[NBH*LM];
__device__ float g_esum[NBH*LM];            // rowsum of eC
__device__ float g_mid0p[NCHUNK*NBH*LM*HD]; // split-K partials of eC @ v_p
__device__ float g_eB[NBH*LM*LM];
__device__ float g_T[NBH*LM*LM];            // pinv temp
__device__ float g_U[NBH*LM*LM];            // pinv temp
__device__ float g_colmax[NBH];
__device__ float g_rowmax[NBH];
__device__ float g_mid[NBH*LM*(HD+1)];      // pi @ (eC @ v_aug), 65 cols
__device__ float g_ctx[BATCH*SEQ*EMB];

// ---------------- tf32 mma helpers ----------------
__device__ __forceinline__ unsigned f2tf32(float x) {
    unsigned r;
    asm("cvt.rna.tf32.f32 %0, %1;" : "=r"(r) : "f"(x));
    return r;
}
__device__ __forceinline__ void mma8(float* c, const unsigned* a, const unsigned* b) {
    asm volatile(
        "mma.sync.aligned.m16n8k8.row.col.f32.tf32.tf32.f32 "
        "{%0,%1,%2,%3},{%4,%5,%6,%7},{%8,%9},{%0,%1,%2,%3};\n"
        : "+f"(c[0]), "+f"(c[1]), "+f"(c[2]), "+f"(c[3])
        : "r"(a[0]), "r"(a[1]), "r"(a[2]), "r"(a[3]), "r"(b[0]), "r"(b[1]));
}
__device__ __forceinline__ uint4 cvt4(float4 v) {
    uint4 u;
    u.x = f2tf32(v.x); u.y = f2tf32(v.y); u.z = f2tf32(v.z); u.w = f2tf32(v.w);
    return u;
}

// ======================= K1: QKV GEMM (tf32, 128x128x32 tiles) =======================
__global__ __launch_bounds__(256) void qkv_gemm_tf32(const float* __restrict__ X,
                                                     const float* __restrict__ W,
                                                     const float* __restrict__ bias) {
    __shared__ unsigned As[128][36];   // [m][k], k-tile 32, pad 36
    __shared__ unsigned Bs[128][36];   // [n][k]
    const int bi = blockIdx.y * 128;
    const int bj = blockIdx.x * 128;
    const int tid = threadIdx.x, warp = tid >> 5, lane = tid & 31;
    const int g = lane >> 2, tig = lane & 3;
    const int wm = (warp & 1) * 64, wn = (warp >> 1) * 32;
    float c[4][4][4] = {};
    const int lr = tid >> 1, lc = (tid & 1) * 16;
    const float* ax = X + (bi + lr) * EMB + lc;
    const float* bx = W + (bj + lr) * EMB + lc;
    float4 pa[4], pb[4];
    #pragma unroll
    for (int i = 0; i < 4; i++) {
        pa[i] = *(const float4*)(ax + i*4);
        pb[i] = *(const float4*)(bx + i*4);
    }
    for (int k0 = 0; k0 < EMB; k0 += 32) {
        #pragma unroll
        for (int i = 0; i < 4; i++) {
            *(uint4*)&As[lr][lc + i*4] = cvt4(pa[i]);
            *(uint4*)&Bs[lr][lc + i*4] = cvt4(pb[i]);
        }
        __syncthreads();
        if (k0 < EMB - 32) {
            #pragma unroll
            for (int i = 0; i < 4; i++) {
                pa[i] = *(const float4*)(ax + k0 + 32 + i*4);
                pb[i] = *(const float4*)(bx + k0 + 32 + i*4);
            }
        }
        #pragma unroll
        for (int ks = 0; ks < 4; ks++) {
            unsigned a[4][4], bb[4][2];
            #pragma unroll
            for (int mf = 0; mf < 4; mf++) {
                const unsigned* p = &As[wm + mf*16 + g][ks*8 + tig];
                a[mf][0] = p[0];
                a[mf][1] = p[8*36];
                a[mf][2] = p[4];
                a[mf][3] = p[8*36 + 4];
            }
            #pragma unroll
            for (int nf = 0; nf < 4; nf++) {
                const unsigned* p = &Bs[wn + nf*8 + g][ks*8 + tig];
                bb[nf][0] = p[0];
                bb[nf][1] = p[4];
            }
            #pragma unroll
            for (int mf = 0; mf < 4; mf++)
                #pragma unroll
                for (int nf = 0; nf < 4; nf++)
                    mma8(c[mf][nf], a[mf], bb[nf]);
        }
        __syncthreads();
    }
    // epilogue: scatter into q/k/v [B][H][N][D], scale q
    #pragma unroll
    for (int mf = 0; mf < 4; mf++) {
        #pragma unroll
        for (int nf = 0; nf < 4; nf++) {
            int gj = bj + wn + nf*8 + tig*2;
            int s  = gj >> 10;
            int hh = (gj >> 6) & 15;
            int dd = gj & 63;
            float b0 = bias[gj], b1 = bias[gj + 1];
            float* dst = (s == 0) ? g_q : (s == 1) ? g_k : g_v;
            float mul = (s == 0) ? QSCALE : 1.0f;
            int gi = bi + wm + mf*16 + g;
            int bb2 = gi >> 11, n = gi & 2047;
            float2 v0 = make_float2((c[mf][nf][0] + b0) * mul, (c[mf][nf][1] + b1) * mul);
            *(float2*)&dst[((bb2*NH + hh)*SEQ + n)*HD + dd] = v0;
            float2 v1 = make_float2((c[mf][nf][2] + b0) * mul, (c[mf][nf][3] + b1) * mul);
            *(float2*)&dst[((bb2*NH + hh)*SEQ + n + 8)*HD + dd] = v1;
        }
    }
}

// ======================= K8: output projection GEMM (tf32, k-tile 32) =======================
__global__ __launch_bounds__(256) void proj_gemm_tf32(const float* __restrict__ W,
                                                      const float* __restrict__ bias,
                                                      float* __restrict__ out) {
    __shared__ unsigned As[128][36];
    __shared__ unsigned Bs[128][36];
    const int bi = blockIdx.y * 128;
    const int bj = blockIdx.x * 128;
    const int tid = threadIdx.x, warp = tid >> 5, lane = tid & 31;
    const int g = lane >> 2, tig = lane & 3;
    const int wm = (warp & 1) * 64, wn = (warp >> 1) * 32;
    float c[4][4][4] = {};
    const int lr = tid >> 1, lc = (tid & 1) * 16;
    const float* ax = g_ctx + (bi + lr) * EMB + lc;
    const float* bx = W + (bj + lr) * EMB + lc;
    float4 pa[4], pb[4];
    #pragma unroll
    for (int i = 0; i < 4; i++) {
        pa[i] = *(const float4*)(ax + i*4);
        pb[i] = *(const float4*)(bx + i*4);
    }
    for (int k0 = 0; k0 < EMB; k0 += 32) {
        #pragma unroll
        for (int i = 0; i < 4; i++) {
            *(uint4*)&As[lr][lc + i*4] = cvt4(pa[i]);
            *(uint4*)&Bs[lr][lc + i*4] = cvt4(pb[i]);
        }
        __syncthreads();
        if (k0 < EMB - 32) {
            #pragma unroll
            for (int i = 0; i < 4; i++) {
                pa[i] = *(const float4*)(ax + k0 + 32 + i*4);
                pb[i] = *(const float4*)(bx + k0 + 32 + i*4);
            }
        }
        #pragma unroll
        for (int ks = 0; ks < 4; ks++) {
            unsigned a[4][4], bb[4][2];
            #pragma unroll
            for (int mf = 0; mf < 4; mf++) {
                const unsigned* p = &As[wm + mf*16 + g][ks*8 + tig];
                a[mf][0] = p[0];
                a[mf][1] = p[8*36];
                a[mf][2] = p[4];
                a[mf][3] = p[8*36 + 4];
            }
            #pragma unroll
            for (int nf = 0; nf < 4; nf++) {
                const unsigned* p = &Bs[wn + nf*8 + g][ks*8 + tig];
                bb[nf][0] = p[0];
                bb[nf][1] = p[4];
            }
            #pragma unroll
            for (int mf = 0; mf < 4; mf++)
                #pragma unroll
                for (int nf = 0; nf < 4; nf++)
                    mma8(c[mf][nf], a[mf], bb[nf]);
        }
        __syncthreads();
    }
    #pragma unroll
    for (int mf = 0; mf < 4; mf++) {
        #pragma unroll
        for (int nf = 0; nf < 4; nf++) {
            int gj = bj + wn + nf*8 + tig*2;
            float b0 = bias[gj], b1 = bias[gj + 1];
            int gi = bi + wm + mf*16 + g;
            float2 v0 = make_float2(c[mf][nf][0] + b0, c[mf][nf][1] + b1);
            *(float2*)&out[gi * EMB + gj] = v0;
            float2 v1 = make_float2(c[mf][nf][2] + b0, c[mf][nf][3] + b1);
            *(float2*)&out[(gi + 8) * EMB + gj] = v1;
        }
    }
}

// ======================= K7: flash attention (tf32 mma, single-buffer K/V reg prefetch) =======================
// Block: 128 query rows of one full-softmax head. 8 warps, each owns 16 rows.
// Dynamic smem: Qs[128][68] + Ks[64][68] + Vs[64][68] + Ps[128][68] = 104448 B (2 CTAs/SM)
#define FLASH_SMEM (68 * 384 * 4)
__global__ __launch_bounds__(256, 2) void flash_tf32() {
    extern __shared__ char smraw[];
    unsigned* Qs = (unsigned*)smraw;          // [128][68]
    unsigned* Ks = Qs + 128 * 68;             // [64][68]
    unsigned* Vs = Ks + 64 * 68;              // [64][68]
    unsigned* Ps = Vs + 64 * 68;              // [128][68] tf32 P
    const int bh = blockIdx.x, qb = blockIdx.y;
    const int b = bh >> 3, h = 8 + (bh & 7);
    const float* qh = g_q + (b*NH + h)*SEQ*HD;
    const float* kh = g_k + (b*NH + h)*SEQ*HD;
    const float* vh = g_v + (b*NH + h)*SEQ*HD;
    const int tid = threadIdx.x, warp = tid >> 5, lane = tid & 31;
    const int g = lane >> 2, tig = lane & 3;
    const int rowA = warp * 16 + g;           // this thread's base row (also rowA+8)

    // load Q tile (128 x 64) as tf32
    {
        int r = tid >> 1, c0 = (tid & 1) * 32;
        const float* src = qh + (qb*128 + r)*HD + c0;
        unsigned* dst = Qs + r*68 + c0;
        #pragma unroll
        for (int i = 0; i < 8; i++)
            *(uint4*)(dst + i*4) = cvt4(*(const float4*)(src + i*4));
    }
    // prefetch K/V tile 0 into registers (tf32-converted)
    const int kvr = tid >> 2, kvc = (tid & 3) * 16;
    uint4 qk[4], qv[4];
    #pragma unroll
    for (int i = 0; i < 4; i++) {
        qk[i] = cvt4(*(const float4*)(kh + kvr*HD + kvc + i*4));
        qv[i] = cvt4(*(const float4*)(vh + kvr*HD + kvc + i*4));
    }

    float o[8][4] = {};
    float mrow[2] = {-1e30f, -1e30f};
    float lrow[2] = {0.f, 0.f};

    for (int t = 0; t < SEQ/64; t++) {
        __syncthreads();   // reads of tile t-1 done (t>0); Q store pre-loop ordered too
        // store prefetched tile t into the single K/V buffer
        #pragma unroll
        for (int i = 0; i < 4; i++) {
            *(uint4*)(Ks + kvr*68 + kvc + i*4) = qk[i];
            *(uint4*)(Vs + kvr*68 + kvc + i*4) = qv[i];
        }
        __syncthreads();   // tile t visible
        // issue LDG for tile t+1; latency hides under both mma phases below
        if (t + 1 < SEQ/64) {
            const float* ks = kh + ((t+1)*64 + kvr)*HD + kvc;
            const float* vs = vh + ((t+1)*64 + kvr)*HD + kvc;
            #pragma unroll
            for (int i = 0; i < 4; i++) {
                qk[i] = cvt4(*(const float4*)(ks + i*4));
                qv[i] = cvt4(*(const float4*)(vs + i*4));
            }
        }

        // S = Q @ K^T for this warp's 16 rows x 64 key-cols
        float s[8][4] = {};
        #pragma unroll
        for (int k8 = 0; k8 < 8; k8++) {
            unsigned a[4];
            const unsigned* qp = Qs + rowA*68 + k8*8;
            a[0] = qp[tig]; a[1] = qp[8*68 + tig];
            a[2] = qp[tig + 4]; a[3] = qp[8*68 + tig + 4];
            #pragma unroll
            for (int nf = 0; nf < 8; nf++) {
                unsigned bfr[2];
                const unsigned* kp = Ks + (nf*8 + g)*68 + k8*8;
                bfr[0] = kp[tig]; bfr[1] = kp[tig + 4];
                mma8(s[nf], a, bfr);
            }
        }
        // online softmax (rows rowA and rowA+8)
        float mx0 = -1e30f, mx1 = -1e30f;
        #pragma unroll
        for (int nf = 0; nf < 8; nf++) {
            mx0 = fmaxf(mx0, fmaxf(s[nf][0], s[nf][1]));
            mx1 = fmaxf(mx1, fmaxf(s[nf][2], s[nf][3]));
        }
        mx0 = fmaxf(mx0, __shfl_xor_sync(0xffffffffu, mx0, 1));
        mx0 = fmaxf(mx0, __shfl_xor_sync(0xffffffffu, mx0, 2));
        mx1 = fmaxf(mx1, __shfl_xor_sync(0xffffffffu, mx1, 1));
        mx1 = fmaxf(mx1, __shfl_xor_sync(0xffffffffu, mx1, 2));
        float mn0 = fmaxf(mrow[0], mx0), mn1 = fmaxf(mrow[1], mx1);
        float sc0 = __expf(mrow[0] - mn0), sc1 = __expf(mrow[1] - mn1);
        float ls0 = 0.f, ls1 = 0.f;
        #pragma unroll
        for (int nf = 0; nf < 8; nf++) {
            float p0 = __expf(s[nf][0] - mn0);
            float p1 = __expf(s[nf][1] - mn0);
            float p2 = __expf(s[nf][2] - mn1);
            float p3 = __expf(s[nf][3] - mn1);
            ls0 += p0 + p1; ls1 += p2 + p3;
            uint2 u0; u0.x = f2tf32(p0); u0.y = f2tf32(p1);
            *(uint2*)(Ps + rowA*68 + nf*8 + tig*2) = u0;
            uint2 u1; u1.x = f2tf32(p2); u1.y = f2tf32(p3);
            *(uint2*)(Ps + (rowA + 8)*68 + nf*8 + tig*2) = u1;
        }
        ls0 += __shfl_xor_sync(0xffffffffu, ls0, 1);
        ls0 += __shfl_xor_sync(0xffffffffu, ls0, 2);
        ls1 += __shfl_xor_sync(0xffffffffu, ls1, 1);
        ls1 += __shfl_xor_sync(0xffffffffu, ls1, 2);
        lrow[0] = lrow[0]*sc0 + ls0;
        lrow[1] = lrow[1]*sc1 + ls1;
        mrow[0] = mn0; mrow[1] = mn1;
        #pragma unroll
        for (int nf = 0; nf < 8; nf++) {
            o[nf][0] *= sc0; o[nf][1] *= sc0;
            o[nf][2] *= sc1; o[nf][3] *= sc1;
        }
        __syncwarp();   // P written (own warp's rows) before fragment reload

        // out += P @ V
        #pragma unroll
        for (int k8 = 0; k8 < 8; k8++) {
            unsigned a[4];
            const unsigned* pp = Ps + rowA*68 + k8*8;
            a[0] = pp[tig];
            a[1] = pp[8*68 + tig];
            a[2] = pp[tig + 4];
            a[3] = pp[8*68 + tig + 4];
            #pragma unroll
            for (int nf = 0; nf < 8; nf++) {
                unsigned bfr[2];
                const unsigned* vp = Vs + (k8*8 + tig)*68 + nf*8 + g;
                bfr[0] = vp[0]; bfr[1] = vp[4*68];
                mma8(o[nf], a, bfr);
            }
        }
    }
    // epilogue
    float inv0 = 1.0f / lrow[0], inv1 = 1.0f / lrow[1];
    int n0 = qb*128 + rowA;
    #pragma unroll
    for (int nf = 0; nf < 8; nf++) {
        int d = nf*8 + tig*2;
        float2 v0 = make_float2(o[nf][0]*inv0, o[nf][1]*inv0);
        *(float2*)&g_ctx[(b*SEQ + n0)*EMB + h*HD + d] = v0;
        float2 v1 = make_float2(o[nf][2]*inv1, o[nf][3]*inv1);
        *(float2*)&g_ctx[(b*SEQ + n0 + 8)*EMB + h*HD + d] = v1;
    }
}

// ======================= K2: SC = q_m @ k^T (tf32 mma, 64x64 tile) =======================
__global__ __launch_bounds__(256) void sc_tf32() {
    const int bh = blockIdx.x;               // b*8+h
    const int b = bh >> 3, h = bh & 7;
    const int n0 = blockIdx.y * 64;
    const float* qh = g_q + (b*NH + h)*SEQ*HD;
    const float* kh = g_k + (b*NH + h)*SEQ*HD;
    __shared__ unsigned Qm[64][68];          // [m][d] landmark rows (d=64, pad 68)
    __shared__ unsigned Kn[64][68];          // [n][d]
    const int tid = threadIdx.x, warp = tid >> 5, lane = tid & 31;
    const int g = lane >> 2, tig = lane & 3;
    {
        int r = tid >> 2, c = (tid & 3) * 16;
        const float* qs = qh + (r*LSTRIDE)*HD + c;
        const float* ks = kh + (n0 + r)*HD + c;
        #pragma unroll
        for (int i = 0; i < 4; i++) {
            *(uint4*)&Qm[r][c + i*4] = cvt4(*(const float4*)(qs + i*4));
            *(uint4*)&Kn[r][c + i*4] = cvt4(*(const float4*)(ks + i*4));
        }
    }
    __syncthreads();
    const int wm = (warp & 3) * 16, wn = (warp >> 2) * 32;
    float c4[4][4] = {};
    #pragma unroll
    for (int k8 = 0; k8 < 8; k8++) {
        unsigned a[4];
        a[0] = Qm[wm + g][k8*8 + tig];
        a[1] = Qm[wm + g + 8][k8*8 + tig];
        a[2] = Qm[wm + g][k8*8 + tig + 4];
        a[3] = Qm[wm + g + 8][k8*8 + tig + 4];
        #pragma unroll
        for (int nf = 0; nf < 4; nf++) {
            unsigned bb[2];
            bb[0] = Kn[wn + nf*8 + g][k8*8 + tig];
            bb[1] = Kn[wn + nf*8 + g][k8*8 + tig + 4];
            mma8(c4[nf], a, bb);
        }
    }
    float* scp = g_SC + bh*LM*SEQ;
    #pragma unroll
    for (int nf = 0; nf < 4; nf++) {
        int n = n0 + wn + nf*8 + tig*2;
        *(float2*)&scp[(wm + g)*SEQ + n]     = make_float2(c4[nf][0], c4[nf][1]);
        *(float2*)&scp[(wm + g + 8)*SEQ + n] = make_float2(c4[nf][2], c4[nf][3]);
    }
}

// ============== K3: per-row max + exp-sum of SC ==============
__global__ __launch_bounds__(256) void rowstats_kernel() {
    const int row = blockIdx.x;              // bh*64 + m
    const float* sp = g_SC + row * SEQ;
    __shared__ float red[256];
    const int tid = threadIdx.x;
    float mx = -1e30f;
    for (int n = tid; n < SEQ; n += 256) mx = fmaxf(mx, sp[n]);
    red[tid] = mx; __syncthreads();
    for (int o = 128; o > 0; o >>= 1) {
        if (tid < o) red[tid] = fmaxf(red[tid], red[tid+o]);
        __syncthreads();
    }
    const float m = red[0];
    __syncthreads();
    float s = 0.f;
    for (int n = tid; n < SEQ; n += 256) s += __expf(sp[n] - m);
    red[tid] = s; __syncthreads();
    for (int o = 128; o > 0; o >>= 1) {
        if (tid < o) red[tid] += red[tid+o];
        __syncthreads();
    }
    if (tid == 0) { g_scmax[row] = m; g_esum[row] = red[0]; }
}

// ============== K4: split-K partials of eC @ v_p (tf32 mma) ==============
__global__ __launch_bounds__(256) void ecv_tf32() {
    const int bh = blockIdx.x;
    const int b = bh >> 3, h = bh & 7;
    const int chunk = blockIdx.y;            // 0..15 -> n range of 128
    const float* vh = g_v + (b*NH + h)*SEQ*HD;
    const float* scp = g_SC + bh*LM*SEQ;
    __shared__ unsigned Et[64][68];          // [n_local][m]  exp values, tf32
    __shared__ unsigned Vs[64][68];          // [n_local][d]  tf32
    __shared__ float mx_s[64];
    const int tid = threadIdx.x, warp = tid >> 5, lane = tid & 31;
    const int g = lane >> 2, tig = lane & 3;
    const int wm = (warp & 3) * 16, wn = (warp >> 2) * 32;
    if (tid < 64) mx_s[tid] = g_scmax[bh*LM + tid];
    float acc[4][4] = {};
    for (int sub = 0; sub < 2; sub++) {
        const int nbase = chunk*128 + sub*64;
        __syncthreads();
        for (int i = tid; i < 64*16; i += 256) {
            int m = i >> 4; int s = (i & 15) * 4;
            float mxv = mx_s[m];
            float4 a = *(const float4*)&scp[m*SEQ + nbase + s];
            Et[s+0][m] = f2tf32(__expf(a.x - mxv));
            Et[s+1][m] = f2tf32(__expf(a.y - mxv));
            Et[s+2][m] = f2tf32(__expf(a.z - mxv));
            Et[s+3][m] = f2tf32(__expf(a.w - mxv));
        }
        {
            int r = tid >> 2, c = (tid & 3) * 16;
            const float* vs = vh + (nbase + r)*HD + c;
            #pragma unroll
            for (int i = 0; i < 4; i++)
                *(uint4*)&Vs[r][c + i*4] = cvt4(*(const float4*)(vs + i*4));
        }
        __syncthreads();
        #pragma unroll
        for (int k8 = 0; k8 < 8; k8++) {
            unsigned a[4];
            a[0] = Et[k8*8 + tig][wm + g];
            a[1] = Et[k8*8 + tig][wm + g + 8];
            a[2] = Et[k8*8 + tig + 4][wm + g];
            a[3] = Et[k8*8 + tig + 4][wm + g + 8];
            #pragma unroll
            for (int nf = 0; nf < 4; nf++) {
                unsigned bb[2];
                int d = wn + nf*8 + g;
                bb[0] = Vs[k8*8 + tig][d];
                bb[1] = Vs[k8*8 + tig + 4][d];
                mma8(acc[nf], a, bb);
            }
        }
    }
    float* dst = g_mid0p + (chunk*NBH + bh)*LM*HD;
    #pragma unroll
    for (int nf = 0; nf < 4; nf++) {
        int d = wn + nf*8 + tig*2;
        *(float2*)&dst[(wm + g)*HD + d]     = make_float2(acc[nf][0], acc[nf][1]);
        *(float2*)&dst[(wm + g + 8)*HD + d] = make_float2(acc[nf][2], acc[nf][3]);
    }
}

// ============== K5a: SB, eB, row/col-sum maxima ==============
__global__ __launch_bounds__(256) void sb_kernel() {
    const int bh = blockIdx.x;
    const int b = bh >> 3, h = bh & 7;
    const float* qh = g_q + (b*NH + h)*SEQ*HD;
    const float* kh = g_k + (b*NH + h)*SEQ*HD;
    __shared__ float Qt[64][64];             // [d][m], later reused as EB[m][k]
    __shared__ float Kt[64][64];             // [d][k]
    __shared__ float red[64];
    const int tid = threadIdx.x;
    for (int i = tid; i < 64*16; i += 256) {
        int r = i >> 4; int s = (i & 15) * 4;
        float4 a = *(const float4*)&qh[(r*LSTRIDE)*HD + s];
        Qt[s+0][r]=a.x; Qt[s+1][r]=a.y; Qt[s+2][r]=a.z; Qt[s+3][r]=a.w;
        float4 bb = *(const float4*)&kh[(r*LSTRIDE)*HD + s];
        Kt[s+0][r]=bb.x; Kt[s+1][r]=bb.y; Kt[s+2][r]=bb.z; Kt[s+3][r]=bb.w;
    }
    __syncthreads();
    const int tx = tid & 15, ty = tid >> 4;
    const int m0 = ty*4, k0 = tx*4;
    float acc[4][4] = {};
    #pragma unroll 8
    for (int d = 0; d < 64; d++) {
        float4 a = *(const float4*)&Qt[d][m0];
        float4 bb = *(const float4*)&Kt[d][k0];
        float Ar[4] = {a.x,a.y,a.z,a.w};
        float Br[4] = {bb.x,bb.y,bb.z,bb.w};
        #pragma unroll
        for (int ii = 0; ii < 4; ii++)
            #pragma unroll
            for (int jj = 0; jj < 4; jj++)
                acc[ii][jj] += Ar[ii]*Br[jj];
    }
    __syncthreads();                         // Qt now dead -> reuse as EB
    float (*EB)[64] = Qt;
    #pragma unroll
    for (int ii = 0; ii < 4; ii++) {
        float mx = g_scmax[bh*LM + m0 + ii];
        #pragma unroll
        for (int jj = 0; jj < 4; jj++) {
            float e = __expf(fmaxf(acc[ii][jj] - mx, -88.0f));
            EB[m0+ii][k0+jj] = e;
            g_eB[bh*LM*LM + (m0+ii)*LM + k0 + jj] = e;
        }
    }
    __syncthreads();
    if (tid < 64) {                          // row sums (reference "col")
        float s = 0.f;
        for (int k = 0; k < 64; k++) s += EB[tid][k];
        red[tid] = s;
    }
    __syncthreads();
    if (tid == 0) {
        float mx = red[0];
        for (int i = 1; i < 64; i++) mx = fmaxf(mx, red[i]);
        g_colmax[bh] = mx;
    }
    __syncthreads();
    if (tid < 64) {                          // col sums (reference "row")
        float s = 0.f;
        for (int m = 0; m < 64; m++) s += EB[m][tid];
        red[tid] = s;
    }
    __syncthreads();
    if (tid == 0) {
        float mx = red[0];
        for (int i = 1; i < 64; i++) mx = fmaxf(mx, red[i]);
        g_rowmax[bh] = mx;
    }
}

// ============== K5b: Moore-Penrose pinv + mid = pi @ (eC@v_aug) ==============
__global__ __launch_bounds__(1024) void pinv_kernel() {
    const int bh = blockIdx.x;
    const int h = bh & 7;
    __shared__ float Z[64][64];
    __shared__ float XZ[64][64];
    const int tid = threadIdx.x;
    const int i  = tid >> 4;
    const int j0 = (tid & 15) * 4;
    const float* Xg = g_eB + bh*LM*LM;
    float* Tg = g_T + bh*LM*LM;
    float* Ug = g_U + bh*LM*LM;

    // denom: max over batch per head
    const float colM = fmaxf(g_colmax[h], g_colmax[8 + h]);
    const float rowM = fmaxf(g_rowmax[h], g_rowmax[8 + h]);
    const float rden = 1.0f / (colM * rowM);

    // z = x^T / denom
    #pragma unroll
    for (int jj = 0; jj < 4; jj++)
        Z[i][j0+jj] = Xg[(j0+jj)*64 + i] * rden;
    __syncthreads();

    for (int it = 0; it < 6; it++) {
        {
            float a0=0,a1=0,a2=0,a3=0;
            for (int k = 0; k < 64; k++) {
                float a = Xg[i*64 + k];
                float4 bz = *(const float4*)&Z[k][j0];
                a0 += a*bz.x; a1 += a*bz.y; a2 += a*bz.z; a3 += a*bz.w;
            }
            XZ[i][j0+0]=a0; XZ[i][j0+1]=a1; XZ[i][j0+2]=a2; XZ[i][j0+3]=a3;
        }
        __syncthreads();
        {
            float a0=0,a1=0,a2=0,a3=0;
            for (int k = 0; k < 64; k++) {
                float a = XZ[i][k];
                float4 bz = *(const float4*)&XZ[k][j0];
                a0 += a*bz.x; a1 += a*bz.y; a2 += a*bz.z; a3 += a*bz.w;
            }
            float4 xz4 = *(const float4*)&XZ[i][j0];
            float4 o = make_float4(7.f*xz4.x - a0, 7.f*xz4.y - a1,
                                   7.f*xz4.z - a2, 7.f*xz4.w - a3);
            *(float4*)&Tg[i*64 + j0] = o;
        }
        __syncthreads();
        {
            float a0=0,a1=0,a2=0,a3=0;
            for (int k = 0; k < 64; k++) {
                float a = XZ[i][k];
                float4 bz = *(const float4*)&Tg[k*64 + j0];
                a0 += a*bz.x; a1 += a*bz.y; a2 += a*bz.z; a3 += a*bz.w;
            }
            float4 xz4 = *(const float4*)&XZ[i][j0];
            float4 o = make_float4(15.f*xz4.x - a0, 15.f*xz4.y - a1,
                                   15.f*xz4.z - a2, 15.f*xz4.w - a3);
            *(float4*)&Ug[i*64 + j0] = o;
        }
        __syncthreads();
        {
            float a0=0,a1=0,a2=0,a3=0;
            for (int k = 0; k < 64; k++) {
                float a = Z[i][k];
                float4 bz = *(const float4*)&Ug[k*64 + j0];
                a0 += a*bz.x; a1 += a*bz.y; a2 += a*bz.z; a3 += a*bz.w;
            }
            float4 z4 = *(const float4*)&Z[i][j0];
            float4 o = make_float4(0.25f*(13.f*z4.x - a0), 0.25f*(13.f*z4.y - a1),
                                   0.25f*(13.f*z4.z - a2), 0.25f*(13.f*z4.w - a3));
            *(float4*)&Tg[i*64 + j0] = o;
        }
        __syncthreads();
        *(float4*)&Z[i][j0] = *(const float4*)&Tg[i*64 + j0];
        __syncthreads();
    }

    {
        float4 s = make_float4(0,0,0,0);
        for (int c = 0; c < NCHUNK; c++) {
            float4 p = *(const float4*)&g_mid0p[(c*NBH + bh)*LM*HD + i*64 + j0];
            s.x += p.x; s.y += p.y; s.z += p.z; s.w += p.w;
        }
        *(float4*)&XZ[i][j0] = s;
    }
    __syncthreads();
    {
        float a0=0,a1=0,a2=0,a3=0;
        for (int k = 0; k < 64; k++) {
            float a = Z[i][k];
            float4 bz = *(const float4*)&XZ[k][j0];
            a0 += a*bz.x; a1 += a*bz.y; a2 += a*bz.z; a3 += a*bz.w;
        }
        float* mp = g_mid + bh*LM*(HD+1) + i*(HD+1) + j0;
        mp[0]=a0; mp[1]=a1; mp[2]=a2; mp[3]=a3;
    }
    if (tid < 64) {
        float s = 0.f;
        for (int k = 0; k < 64; k++) s += Z[tid][k] * g_esum[bh*LM + k];
        g_mid[bh*LM*(HD+1) + tid*(HD+1) + 64] = s;
    }
}

// ============== K6: out_p = softmax-ish(q_p@k_m^T) @ mid, divide ==============
__global__ __launch_bounds__(256) void nystrom_out_kernel() {
    const int bh = blockIdx.x;
    const int b = bh >> 3, h = bh & 7;
    const int qb = blockIdx.y;               // 0..31
    const float* qh = g_q + (b*NH + h)*SEQ*HD;
    __shared__ float A1[64][64];             // Qt[d][r] then P[r][k]
    __shared__ float A2[64][64];             // Kmt[d][k] then Ms[k][j]
    __shared__ float rm[64], den[64], mcol[64];
    const int tid = threadIdx.x;
    for (int i = tid; i < 64*16; i += 256) {
        int r = i >> 4; int s = (i & 15) * 4;
        float4 a = *(const float4*)&qh[(qb*64 + r)*HD + s];
        A1[s+0][r]=a.x; A1[s+1][r]=a.y; A1[s+2][r]=a.z; A1[s+3][r]=a.w;
        const float* kh = g_k + (b*NH + h)*SEQ*HD;
        float4 bb = *(const float4*)&kh[(r*LSTRIDE)*HD + s];
        A2[s+0][r]=bb.x; A2[s+1][r]=bb.y; A2[s+2][r]=bb.z; A2[s+3][r]=bb.w;
    }
    __syncthreads();
    const int tx = tid & 15, ty = tid >> 4;
    const int r0 = ty*4, k0 = tx*4;
    float acc[4][4] = {};
    #pragma unroll 8
    for (int d = 0; d < 64; d++) {
        float4 a = *(const float4*)&A1[d][r0];
        float4 bb = *(const float4*)&A2[d][k0];
        float Ar[4] = {a.x,a.y,a.z,a.w};
        float Br[4] = {bb.x,bb.y,bb.z,bb.w};
        #pragma unroll
        for (int ii = 0; ii < 4; ii++)
            #pragma unroll
            for (int jj = 0; jj < 4; jj++)
                acc[ii][jj] += Ar[ii]*Br[jj];
    }
    __syncthreads();
    #pragma unroll
    for (int ii = 0; ii < 4; ii++)
        #pragma unroll
        for (int jj = 0; jj < 4; jj++)
            A1[r0+ii][k0+jj] = acc[ii][jj];
    const float* mp = g_mid + bh*LM*(HD+1);
    for (int i = tid; i < 4096; i += 256) {
        int k = i >> 6, j = i & 63;
        A2[k][j] = mp[k*(HD+1) + j];
    }
    if (tid < 64) mcol[tid] = mp[tid*(HD+1) + 64];
    __syncthreads();
    if (tid < 64) {
        float mx = -1e30f;
        for (int k = 0; k < 64; k++) mx = fmaxf(mx, A1[tid][k]);
        rm[tid] = mx;
    }
    __syncthreads();
    for (int i = tid; i < 4096; i += 256) {
        int r = i >> 6, k = i & 63;
        A1[r][k] = __expf(A1[r][k] - rm[r]);
    }
    __syncthreads();
    if (tid < 64) {
        float s = 0.f;
        for (int k = 0; k < 64; k++) s += A1[tid][k] * mcol[k];
        den[tid] = s;
    }
    __syncthreads();
    float o[4][4] = {};
    #pragma unroll 8
    for (int k = 0; k < 64; k++) {
        float4 bb = *(const float4*)&A2[k][k0];
        float Br[4] = {bb.x,bb.y,bb.z,bb.w};
        #pragma unroll
        for (int ii = 0; ii < 4; ii++) {
            float a = A1[r0+ii][k];
            #pragma unroll
            for (int jj = 0; jj < 4; jj++)
                o[ii][jj] += a * Br[jj];
        }
    }
    #pragma unroll
    for (int ii = 0; ii < 4; ii++) {
        float inv = 1.0f / fmaxf(den[r0+ii], 1e-8f);
        int n = qb*64 + r0 + ii;
        float4 v = make_float4(o[ii][0]*inv, o[ii][1]*inv, o[ii][2]*inv, o[ii][3]*inv);
        *(float4*)&g_ctx[(b*SEQ + n)*EMB + h*HD + k0] = v;
    }
}

// =================================================================================
extern "C" void kernel_launch(void* const* d_in, const int* in_sizes, int n_in,
                              void* d_out, int out_size) {
    (void)in_sizes; (void)n_in; (void)out_size;
    const float* x      = (const float*)d_in[0];
    const float* qkv_w  = (const float*)d_in[1];
    const float* qkv_b  = (const float*)d_in[2];
    const float* proj_w = (const float*)d_in[3];
    const float* proj_b = (const float*)d_in[4];
    float* out = (float*)d_out;

    cudaFuncSetAttribute(flash_tf32, cudaFuncAttributeMaxDynamicSharedMemorySize, FLASH_SMEM);

    qkv_gemm_tf32<<<dim3(24, 32), 256>>>(x, qkv_w, qkv_b);
    sc_tf32<<<dim3(NBH, SEQ/64), 256>>>();
    rowstats_kernel<<<NBH*LM, 256>>>();
    ecv_tf32<<<dim3(NBH, NCHUNK), 256>>>();
    sb_kernel<<<NBH, 256>>>();
    pinv_kernel<<<NBH, 1024>>>();
    nystrom_out_kernel<<<dim3(NBH, SEQ/64), 256>>>();
    flash_tf32<<<dim3(NBH, SEQ/128), 256, FLASH_SMEM>>>();
    proj_gemm_tf32<<<dim3(8, 32), 256>>>(proj_w, proj_b, out);
}